// round 6
// baseline (speedup 1.0000x reference)
#include <cuda_runtime.h>
#include <cuda_fp16.h>
#include <cuda_fp8.h>
#include <math.h>
#include <stdint.h>

// ---------------------------------------------------------------------------
// Problem constants
// ---------------------------------------------------------------------------
#define B_     4
#define NTOK   8192
#define MTOK   1024
#define DMODEL 1024
#define H_     16
#define DH     64
#define EPSF   1e-6f
#define NCHUNK 9               // 9216 / 1024

// Split scales: A-side (activations ~N(0,1)), B-side (weights ~N(0,1/1024))
#define ASL 4096.0f            // 2^12 for A fp16-residue -> e4m3
#define ASH 4.0f               // 2^2  for A value -> e4m3
#define BSL 32768.0f           // 2^15 for B fp16-residue -> e4m3
#define BSH 32.0f              // 2^5  for B value -> e4m3
#define FOLD (1.0f / 131072.0f)  // 2^-17 = 1/(ASL*BSH) = 1/(ASH*BSL)

// ---------------------------------------------------------------------------
// Scratch (static device globals; no allocation allowed)
// ---------------------------------------------------------------------------
__device__ float g_qkv [(size_t)B_ * NTOK * 3 * DMODEL];
__device__ float g_ckv [(size_t)B_ * MTOK * 2 * DMODEL];
__device__ float g_kvp [(size_t)NCHUNK * 64 * DH * DH];
__device__ float g_ksp [(size_t)NCHUNK * 64 * DH];
__device__ float g_kv  [64 * DH * DH];
__device__ float g_ksum[64 * DH];
// A-side split buffers (x / attn reuse), y, weights
__device__ __half  g_xh [(size_t)B_ * NTOK * DMODEL];
__device__ uint8_t g_xl8[(size_t)B_ * NTOK * DMODEL];
__device__ uint8_t g_xh8[(size_t)B_ * NTOK * DMODEL];
__device__ __half  g_yh [(size_t)B_ * MTOK * DMODEL];
__device__ uint8_t g_yl8[(size_t)B_ * MTOK * DMODEL];
__device__ uint8_t g_yh8[(size_t)B_ * MTOK * DMODEL];
__device__ __half  g_wh [(size_t)3 * DMODEL * DMODEL];
__device__ uint8_t g_wl8[(size_t)3 * DMODEL * DMODEL];
__device__ uint8_t g_wh8[(size_t)3 * DMODEL * DMODEL];

// ---------------------------------------------------------------------------
// PTX helpers
// ---------------------------------------------------------------------------
__device__ __forceinline__ uint32_t smem_u32(const void* p) {
    uint32_t a;
    asm("{ .reg .u64 t; cvta.to.shared.u64 t, %1; cvt.u32.u64 %0, t; }"
        : "=r"(a) : "l"(p));
    return a;
}
__device__ __forceinline__ void cp16(uint32_t s, const void* g) {
    asm volatile("cp.async.cg.shared.global [%0], [%1], 16;" :: "r"(s), "l"(g));
}
#define CP_COMMIT() asm volatile("cp.async.commit_group;" ::: "memory")
#define CP_WAIT1()  asm volatile("cp.async.wait_group 1;" ::: "memory")
#define CP_WAIT0()  asm volatile("cp.async.wait_group 0;" ::: "memory")

__device__ __forceinline__ void ldsm_x4(uint32_t& r0, uint32_t& r1,
                                        uint32_t& r2, uint32_t& r3, uint32_t addr) {
    asm volatile("ldmatrix.sync.aligned.m8n8.x4.shared.b16 {%0,%1,%2,%3}, [%4];"
                 : "=r"(r0), "=r"(r1), "=r"(r2), "=r"(r3) : "r"(addr));
}
__device__ __forceinline__ void mma_f16(float* c, const uint32_t* a, const uint32_t* b) {
    asm volatile(
        "mma.sync.aligned.m16n8k16.row.col.f32.f16.f16.f32 "
        "{%0,%1,%2,%3}, {%4,%5,%6,%7}, {%8,%9}, {%0,%1,%2,%3};"
        : "+f"(c[0]), "+f"(c[1]), "+f"(c[2]), "+f"(c[3])
        : "r"(a[0]), "r"(a[1]), "r"(a[2]), "r"(a[3]), "r"(b[0]), "r"(b[1]));
}
__device__ __forceinline__ void mma_e4m3(float* c, const uint32_t* a, const uint32_t* b) {
    asm volatile(
        "mma.sync.aligned.m16n8k32.row.col.f32.e4m3.e4m3.f32 "
        "{%0,%1,%2,%3}, {%4,%5,%6,%7}, {%8,%9}, {%0,%1,%2,%3};"
        : "+f"(c[0]), "+f"(c[1]), "+f"(c[2]), "+f"(c[3])
        : "r"(a[0]), "r"(a[1]), "r"(a[2]), "r"(a[3]), "r"(b[0]), "r"(b[1]));
}
__device__ __forceinline__ uint8_t to_e4m3(float v) {
    return (uint8_t)__nv_cvt_float_to_fp8(v, __NV_SATFINITE, __NV_E4M3);
}

// ---------------------------------------------------------------------------
// Split fp32 -> fp16 hi + e4m3 scaled-residue + e4m3 scaled-value
// ---------------------------------------------------------------------------
__global__ void __launch_bounds__(256) conv_split(
    const float* __restrict__ in, __half* __restrict__ h,
    uint8_t* __restrict__ l8, uint8_t* __restrict__ h8, int n4,
    float sl, float sh)
{
    const int i = blockIdx.x * blockDim.x + threadIdx.x;
    if (i >= n4) return;
    const float4 v = reinterpret_cast<const float4*>(in)[i];
    const __half a0 = __float2half(v.x);
    const __half a1 = __float2half(v.y);
    const __half a2 = __float2half(v.z);
    const __half a3 = __float2half(v.w);
    reinterpret_cast<__half2*>(h)[2 * i]     = __halves2half2(a0, a1);
    reinterpret_cast<__half2*>(h)[2 * i + 1] = __halves2half2(a2, a3);
    uchar4 lq;
    lq.x = to_e4m3((v.x - __half2float(a0)) * sl);
    lq.y = to_e4m3((v.y - __half2float(a1)) * sl);
    lq.z = to_e4m3((v.z - __half2float(a2)) * sl);
    lq.w = to_e4m3((v.w - __half2float(a3)) * sl);
    reinterpret_cast<uchar4*>(l8)[i] = lq;
    uchar4 hq;
    hq.x = to_e4m3(v.x * sh);
    hq.y = to_e4m3(v.y * sh);
    hq.z = to_e4m3(v.z * sh);
    hq.w = to_e4m3(v.w * sh);
    reinterpret_cast<uchar4*>(h8)[i] = hq;
}

// ---------------------------------------------------------------------------
// Transpose + split weights: w[1024, C] fp32 -> [C, 1024] fp16 + e4m3 pair
// ---------------------------------------------------------------------------
__global__ void __launch_bounds__(256) conv_w_t(
    const float* __restrict__ w, __half* __restrict__ th,
    uint8_t* __restrict__ tl8, uint8_t* __restrict__ th8, int C)
{
    __shared__ float s[32][33];
    const int c0 = blockIdx.x * 32;
    const int k0 = blockIdx.y * 32;
    const int tx = threadIdx.x;
    const int ty = threadIdx.y;
#pragma unroll
    for (int i = 0; i < 32; i += 8)
        s[ty + i][tx] = w[(size_t)(k0 + ty + i) * C + c0 + tx];
    __syncthreads();
#pragma unroll
    for (int i = 0; i < 32; i += 8) {
        const float v = s[tx][ty + i];
        const __half hv = __float2half(v);
        const size_t o = (size_t)(c0 + ty + i) * DMODEL + k0 + tx;
        th[o]  = hv;
        tl8[o] = to_e4m3((v - __half2float(hv)) * BSL);
        th8[o] = to_e4m3(v * BSH);
    }
}

// ---------------------------------------------------------------------------
// GEMM: fp16-hi mma + e4m3 correction mma (2 slot-units), fused RMSNorm+ReLU.
//   C[M,Nd] = A[M,1024] @ Bt[Nd,1024]^T + bias  (then norm for n0 < nlimit)
// 128x128 tile, BK=32, 256 threads (8 warps 2x4), warp tile 64x32,
// cp.async double buffer.
// ---------------------------------------------------------------------------
#define BM  128
#define BN  128
#define ROWH 80      // fp16 tile row stride (64B data + 16 pad)
#define ROWQ 48      // fp8 tile row stride (32B data + 16 pad)
#define S_AH 0
#define S_BH 10240
#define S_AL 20480
#define S_A8 26624
#define S_BL 32768
#define S_B8 38912
#define STAGE 45056
#define GEMM_SMEM (2 * STAGE)   // 90112; epilogue needs 128*132*4+1024=68608
#define CSTRIDE 132

__global__ void __launch_bounds__(256, 1) gemm_mma(
    const __half* __restrict__ Ah, const uint8_t* __restrict__ Al8,
    const uint8_t* __restrict__ Ah8,
    const __half* __restrict__ Bh, const uint8_t* __restrict__ Bl8,
    const uint8_t* __restrict__ Bh8,
    const float* __restrict__ bias, float* __restrict__ C, int Nd,
    int nlimit, const float* __restrict__ wq, const float* __restrict__ wk)
{
    extern __shared__ char smem[];
    const uint32_t sb = smem_u32(smem);
    const int tid  = threadIdx.x;
    const int wid  = tid >> 5;
    const int lane = tid & 31;
    const int m0 = blockIdx.y * BM;
    const int n0 = blockIdx.x * BN;

    const __half*  gAh = Ah  + (size_t)m0 * 1024;
    const uint8_t* gAl = Al8 + (size_t)m0 * 1024;
    const uint8_t* gA8 = Ah8 + (size_t)m0 * 1024;
    const __half*  gBh = Bh  + (size_t)n0 * 1024;
    const uint8_t* gBl = Bl8 + (size_t)n0 * 1024;
    const uint8_t* gB8 = Bh8 + (size_t)n0 * 1024;

    const int lr = tid >> 1;        // 0..127 (row)
    const int hc = tid & 1;         // half selector

    auto load_tile = [&](int buf, int kt) {
        const uint32_t s = sb + buf * STAGE;
        const size_t go = (size_t)lr * 1024 + kt * 32;
        // fp16 tiles: 64B rows, 2 cp16 per thread each
        cp16(s + S_AH + lr * ROWH + hc * 32,      gAh + go + hc * 16);
        cp16(s + S_AH + lr * ROWH + hc * 32 + 16, gAh + go + hc * 16 + 8);
        cp16(s + S_BH + lr * ROWH + hc * 32,      gBh + go + hc * 16);
        cp16(s + S_BH + lr * ROWH + hc * 32 + 16, gBh + go + hc * 16 + 8);
        // fp8 tiles: 32B rows, 1 cp16 per thread each
        cp16(s + S_AL + lr * ROWQ + hc * 16, gAl + go + hc * 16);
        cp16(s + S_A8 + lr * ROWQ + hc * 16, gA8 + go + hc * 16);
        cp16(s + S_BL + lr * ROWQ + hc * 16, gBl + go + hc * 16);
        cp16(s + S_B8 + lr * ROWQ + hc * 16, gB8 + go + hc * 16);
    };

    const int mbase = (wid >> 2) * 64;
    const int nbase = (wid & 3) * 32;
    const int aRow = mbase + (lane & 15);
    const int aCol = (lane >> 4) * 16;
    const int bRow = nbase + ((lane >> 4) << 3) + (lane & 7);
    const int bCol = ((lane >> 3) & 1) * 16;

    float acc1[4][4][4];   // fp16-hi accumulator
    float acc2[4][4][4];   // fp8 correction accumulator (x 2^17)
#pragma unroll
    for (int i = 0; i < 4; i++)
#pragma unroll
        for (int j = 0; j < 4; j++)
#pragma unroll
            for (int k = 0; k < 4; k++) { acc1[i][j][k] = 0.0f; acc2[i][j][k] = 0.0f; }

    load_tile(0, 0); CP_COMMIT();
    load_tile(1, 1); CP_COMMIT();

    for (int kt = 0; kt < 32; kt++) {
        if (kt < 31) { CP_WAIT1(); } else { CP_WAIT0(); }
        __syncthreads();
        const uint32_t base = sb + (kt & 1) * STAGE;

        // ---- fp16 hi passes (2 x k16) ----
#pragma unroll
        for (int ks = 0; ks < 2; ks++) {
            uint32_t af[4][4], bf[4][2];
#pragma unroll
            for (int mt = 0; mt < 4; mt++)
                ldsm_x4(af[mt][0], af[mt][1], af[mt][2], af[mt][3],
                        base + S_AH + (aRow + mt * 16) * ROWH + ks * 32 + aCol);
#pragma unroll
            for (int p = 0; p < 2; p++) {
                uint32_t t0, t1, t2, t3;
                ldsm_x4(t0, t1, t2, t3,
                        base + S_BH + (bRow + p * 16) * ROWH + ks * 32 + bCol);
                bf[p * 2][0] = t0; bf[p * 2][1] = t1;
                bf[p * 2 + 1][0] = t2; bf[p * 2 + 1][1] = t3;
            }
#pragma unroll
            for (int mt = 0; mt < 4; mt++)
#pragma unroll
                for (int nt = 0; nt < 4; nt++)
                    mma_f16(acc1[mt][nt], af[mt], bf[nt]);
        }

        // ---- fp8 correction 1: (al*2^12) . (b*2^5), k32 covers whole kt ----
        {
            uint32_t af8[4][4], bf8[4][2];
#pragma unroll
            for (int mt = 0; mt < 4; mt++)
                ldsm_x4(af8[mt][0], af8[mt][1], af8[mt][2], af8[mt][3],
                        base + S_AL + (aRow + mt * 16) * ROWQ + aCol);
#pragma unroll
            for (int p = 0; p < 2; p++) {
                uint32_t t0, t1, t2, t3;
                ldsm_x4(t0, t1, t2, t3,
                        base + S_B8 + (bRow + p * 16) * ROWQ + bCol);
                bf8[p * 2][0] = t0; bf8[p * 2][1] = t1;
                bf8[p * 2 + 1][0] = t2; bf8[p * 2 + 1][1] = t3;
            }
#pragma unroll
            for (int mt = 0; mt < 4; mt++)
#pragma unroll
                for (int nt = 0; nt < 4; nt++)
                    mma_e4m3(acc2[mt][nt], af8[mt], bf8[nt]);
        }
        // ---- fp8 correction 2: (a*2^2) . (bl*2^15) ----
        {
            uint32_t af8[4][4], bf8[4][2];
#pragma unroll
            for (int mt = 0; mt < 4; mt++)
                ldsm_x4(af8[mt][0], af8[mt][1], af8[mt][2], af8[mt][3],
                        base + S_A8 + (aRow + mt * 16) * ROWQ + aCol);
#pragma unroll
            for (int p = 0; p < 2; p++) {
                uint32_t t0, t1, t2, t3;
                ldsm_x4(t0, t1, t2, t3,
                        base + S_BL + (bRow + p * 16) * ROWQ + bCol);
                bf8[p * 2][0] = t0; bf8[p * 2][1] = t1;
                bf8[p * 2 + 1][0] = t2; bf8[p * 2 + 1][1] = t3;
            }
#pragma unroll
            for (int mt = 0; mt < 4; mt++)
#pragma unroll
                for (int nt = 0; nt < 4; nt++)
                    mma_e4m3(acc2[mt][nt], af8[mt], bf8[nt]);
        }

        __syncthreads();
        if (kt + 2 < 32) { load_tile(kt & 1, kt + 2); CP_COMMIT(); }
    }

    // ---- Epilogue: fold + bias into smem, fused RMSNorm+ReLU, store ----
    __syncthreads();
    float* cs = (float*)smem;
    float* sc = cs + 128 * CSTRIDE;
    {
        const int erow = lane >> 2;
        const int ecol = (lane & 3) * 2;
#pragma unroll
        for (int nt = 0; nt < 4; nt++) {
            const int col = nbase + nt * 8 + ecol;
            const float bx = bias[n0 + col], by = bias[n0 + col + 1];
#pragma unroll
            for (int mt = 0; mt < 4; mt++) {
                const int r0 = mbase + mt * 16 + erow;
                cs[r0 * CSTRIDE + col]           = acc1[mt][nt][0] + FOLD * acc2[mt][nt][0] + bx;
                cs[r0 * CSTRIDE + col + 1]       = acc1[mt][nt][1] + FOLD * acc2[mt][nt][1] + by;
                cs[(r0 + 8) * CSTRIDE + col]     = acc1[mt][nt][2] + FOLD * acc2[mt][nt][2] + bx;
                cs[(r0 + 8) * CSTRIDE + col + 1] = acc1[mt][nt][3] + FOLD * acc2[mt][nt][3] + by;
            }
        }
    }
    __syncthreads();

    const bool donorm = (n0 < nlimit);
    if (donorm) {
        const int row  = tid >> 1;
        const int head = tid & 1;
        const float* rp = cs + row * CSTRIDE + head * 64;
        float ss = 0.0f;
#pragma unroll
        for (int j = 0; j < 64; j += 4) {
            float4 v = *(const float4*)(rp + j);
            ss += v.x * v.x + v.y * v.y + v.z * v.z + v.w * v.w;
        }
        sc[tid] = rsqrtf(ss * (1.0f / 64.0f) + EPSF);
        __syncthreads();
    }

    const float* wv = (n0 < 1024) ? wq : wk;
#pragma unroll
    for (int i = 0; i < 16; i++) {
        const int idx = i * 256 + tid;
        const int row = idx >> 5;
        const int c4  = (idx & 31) * 4;
        float4 v = *(float4*)(cs + row * CSTRIDE + c4);
        if (donorm) {
            const float s = sc[row * 2 + (c4 >> 6)];
            const float4 w4 = *(const float4*)(wv + (c4 & 63));
            v.x = fmaxf(v.x * s * w4.x, 0.0f);
            v.y = fmaxf(v.y * s * w4.y, 0.0f);
            v.z = fmaxf(v.z * s * w4.z, 0.0f);
            v.w = fmaxf(v.w * s * w4.w, 0.0f);
        }
        *(float4*)(C + (size_t)(m0 + row) * Nd + n0 + c4) = v;
    }
}

// ---------------------------------------------------------------------------
// kv[b,h,d,e] = sum_s k[s,d] v[s,e];  ksum[b,h,d] = sum_s k[s,d]
// ---------------------------------------------------------------------------
#define SCHUNK 1024
#define SSUB   16

__global__ void kv_accum(const float* __restrict__ qkv, const float* __restrict__ ckv,
                         float* __restrict__ kvp, float* __restrict__ ksp)
{
    const int bh = blockIdx.y;
    const int b  = bh >> 4;
    const int h  = bh & 15;
    const int s0 = blockIdx.x * SCHUNK;

    __shared__ float sk[SSUB][DH];
    __shared__ float sv[SSUB][DH];

    const int tid = threadIdx.x;
    const int d   = tid >> 2;
    const int eg  = tid & 3;

    float acc[16];
#pragma unroll
    for (int j = 0; j < 16; j++) acc[j] = 0.0f;
    float ksl = 0.0f;

    for (int st = s0; st < s0 + SCHUNK; st += SSUB) {
        for (int i = tid; i < SSUB * DH; i += 256) {
            const int si = i >> 6;
            const int dd = i & 63;
            const int s  = st + si;
            float kvvk, kvvv;
            if (s < NTOK) {
                const float* row = qkv + (size_t)(b * NTOK + s) * (3 * DMODEL);
                kvvk = row[DMODEL + h * DH + dd];
                kvvv = row[2 * DMODEL + h * DH + dd];
            } else {
                const float* row = ckv + (size_t)(b * MTOK + (s - NTOK)) * (2 * DMODEL);
                kvvk = row[h * DH + dd];
                kvvv = row[DMODEL + h * DH + dd];
            }
            sk[si][dd] = kvvk;
            sv[si][dd] = kvvv;
        }
        __syncthreads();
#pragma unroll
        for (int si = 0; si < SSUB; si++) {
            const float kd = sk[si][d];
            if (eg == 0) ksl += kd;
#pragma unroll
            for (int j = 0; j < 16; j++)
                acc[j] = fmaf(kd, sv[si][eg * 16 + j], acc[j]);
        }
        __syncthreads();
    }

    float* kvpp = kvp + (size_t)blockIdx.x * 64 * DH * DH + (size_t)bh * DH * DH + d * DH + eg * 16;
#pragma unroll
    for (int j = 0; j < 16; j++) kvpp[j] = acc[j];
    if (eg == 0) ksp[(size_t)blockIdx.x * 64 * DH + bh * DH + d] = ksl;
}

__global__ void kv_reduce(const float* __restrict__ kvp, const float* __restrict__ ksp,
                          float* __restrict__ kv, float* __restrict__ ksum)
{
    const int idx = blockIdx.x * blockDim.x + threadIdx.x;
    if (idx < 64 * DH * DH) {
        float s = 0.0f;
#pragma unroll
        for (int c = 0; c < NCHUNK; c++) s += kvp[(size_t)c * 64 * DH * DH + idx];
        kv[idx] = s;
    }
    if (idx < 64 * DH) {
        float s = 0.0f;
#pragma unroll
        for (int c = 0; c < NCHUNK; c++) s += ksp[(size_t)c * 64 * DH + idx];
        ksum[idx] = s;
    }
}

// ---------------------------------------------------------------------------
// attn = (q @ kv) / (q . ksum + eps); writes fp16-hi + fp8 splits directly
// ---------------------------------------------------------------------------
__global__ void attn_apply(const float* __restrict__ qkv, const float* __restrict__ kv,
                           const float* __restrict__ ksum,
                           __half* __restrict__ oh, uint8_t* __restrict__ ol8,
                           uint8_t* __restrict__ oh8)
{
    const int bh = blockIdx.y;
    const int b  = bh >> 4;
    const int h  = bh & 15;

    __shared__ float skv[DH * DH];
    __shared__ float sks[DH];

    const int tid = threadIdx.x;
    for (int i = tid; i < DH * DH; i += 256) skv[i] = kv[(size_t)bh * DH * DH + i];
    if (tid < DH) sks[tid] = ksum[bh * DH + tid];
    __syncthreads();

    const int warp = tid >> 5;
    const int lane = tid & 31;
    const int t0   = blockIdx.x * 64 + warp * 8;

    for (int i = 0; i < 8; i++) {
        const int t = t0 + i;
        const float* qp = qkv + (size_t)(b * NTOK + t) * (3 * DMODEL) + h * DH;
        const float q0 = qp[lane];
        const float q1 = qp[lane + 32];

        float scv = q0 * sks[lane] + q1 * sks[lane + 32];
#pragma unroll
        for (int o = 16; o > 0; o >>= 1) scv += __shfl_xor_sync(0xffffffffu, scv, o);
        const float inv = 1.0f / (scv + EPSF);

        float a0 = 0.0f, a1 = 0.0f;
#pragma unroll
        for (int d = 0; d < 32; d++) {
            const float qd = __shfl_sync(0xffffffffu, q0, d);
            a0 = fmaf(qd, skv[d * DH + lane], a0);
            a1 = fmaf(qd, skv[d * DH + lane + 32], a1);
        }
#pragma unroll
        for (int d = 0; d < 32; d++) {
            const float qd = __shfl_sync(0xffffffffu, q1, d);
            a0 = fmaf(qd, skv[(d + 32) * DH + lane], a0);
            a1 = fmaf(qd, skv[(d + 32) * DH + lane + 32], a1);
        }
        a0 *= inv;
        a1 *= inv;

        const size_t o0 = (size_t)(b * NTOK + t) * DMODEL + h * DH;
        const __half h0 = __float2half(a0);
        const __half h1 = __float2half(a1);
        oh[o0 + lane]       = h0;
        oh[o0 + lane + 32]  = h1;
        ol8[o0 + lane]      = to_e4m3((a0 - __half2float(h0)) * ASL);
        ol8[o0 + lane + 32] = to_e4m3((a1 - __half2float(h1)) * ASL);
        oh8[o0 + lane]      = to_e4m3(a0 * ASH);
        oh8[o0 + lane + 32] = to_e4m3(a1 * ASH);
    }
}

// ---------------------------------------------------------------------------
// Launch
// ---------------------------------------------------------------------------
extern "C" void kernel_launch(void* const* d_in, const int* in_sizes, int n_in,
                              void* d_out, int out_size)
{
    const float* x     = (const float*)d_in[0];
    const float* y     = (const float*)d_in[1];
    const float* w_qkv = (const float*)d_in[2];
    const float* b_qkv = (const float*)d_in[3];
    const float* w_ckv = (const float*)d_in[4];
    const float* b_ckv = (const float*)d_in[5];
    const float* w_out = (const float*)d_in[6];
    const float* b_out = (const float*)d_in[7];
    const float* qn_w  = (const float*)d_in[8];
    const float* kn_w  = (const float*)d_in[9];
    const float* ckn_w = (const float*)d_in[10];
    float* out = (float*)d_out;

    float *p_qkv, *p_ckv, *p_kvp, *p_ksp, *p_kv, *p_ksum;
    __half *p_xh, *p_yh, *p_wh;
    uint8_t *p_xl8, *p_xh8, *p_yl8, *p_yh8, *p_wl8, *p_wh8;
    cudaGetSymbolAddress((void**)&p_qkv,  g_qkv);
    cudaGetSymbolAddress((void**)&p_ckv,  g_ckv);
    cudaGetSymbolAddress((void**)&p_kvp,  g_kvp);
    cudaGetSymbolAddress((void**)&p_ksp,  g_ksp);
    cudaGetSymbolAddress((void**)&p_kv,   g_kv);
    cudaGetSymbolAddress((void**)&p_ksum, g_ksum);
    cudaGetSymbolAddress((void**)&p_xh,   g_xh);
    cudaGetSymbolAddress((void**)&p_xl8,  g_xl8);
    cudaGetSymbolAddress((void**)&p_xh8,  g_xh8);
    cudaGetSymbolAddress((void**)&p_yh,   g_yh);
    cudaGetSymbolAddress((void**)&p_yl8,  g_yl8);
    cudaGetSymbolAddress((void**)&p_yh8,  g_yh8);
    cudaGetSymbolAddress((void**)&p_wh,   g_wh);
    cudaGetSymbolAddress((void**)&p_wl8,  g_wl8);
    cudaGetSymbolAddress((void**)&p_wh8,  g_wh8);

    cudaFuncSetAttribute(gemm_mma, cudaFuncAttributeMaxDynamicSharedMemorySize, GEMM_SMEM);

    const dim3 blk(256);
    const dim3 wblk(32, 8);
    const int MR = B_ * NTOK;   // 32768
    const int YR = B_ * MTOK;   // 4096

    // 1) split x; transpose+split w_qkv; QKV GEMM with fused q/k RMSNorm+ReLU
    conv_split<<<(MR * DMODEL / 4 + 255) / 256, blk>>>(
        x, p_xh, p_xl8, p_xh8, MR * DMODEL / 4, ASL, ASH);
    conv_w_t<<<dim3(3 * DMODEL / 32, DMODEL / 32), wblk>>>(w_qkv, p_wh, p_wl8, p_wh8, 3 * DMODEL);
    gemm_mma<<<dim3(3 * DMODEL / BN, MR / BM), blk, GEMM_SMEM>>>(
        p_xh, p_xl8, p_xh8, p_wh, p_wl8, p_wh8, b_qkv, p_qkv, 3 * DMODEL,
        2048, qn_w, kn_w);

    // 2) split y; transpose+split w_ckv; CKV GEMM with fused c_k RMSNorm+ReLU
    conv_split<<<(YR * DMODEL / 4 + 255) / 256, blk>>>(
        y, p_yh, p_yl8, p_yh8, YR * DMODEL / 4, ASL, ASH);
    conv_w_t<<<dim3(2 * DMODEL / 32, DMODEL / 32), wblk>>>(w_ckv, p_wh, p_wl8, p_wh8, 2 * DMODEL);
    gemm_mma<<<dim3(2 * DMODEL / BN, YR / BM), blk, GEMM_SMEM>>>(
        p_yh, p_yl8, p_yh8, p_wh, p_wl8, p_wh8, b_ckv, p_ckv, 2 * DMODEL,
        1024, ckn_w, ckn_w);

    // 3) kv + k_sum
    kv_accum<<<dim3(NCHUNK, 64), blk>>>(p_qkv, p_ckv, p_kvp, p_ksp);
    kv_reduce<<<(64 * DH * DH + 255) / 256, blk>>>(p_kvp, p_ksp, p_kv, p_ksum);

    // 4) attn (writes fp16/fp8 splits directly into x-side buffers)
    attn_apply<<<dim3(NTOK / 64, 64), blk>>>(p_qkv, p_kv, p_ksum, p_xh, p_xl8, p_xh8);

    // 5) transpose+split w_out; output GEMM (no norm)
    conv_w_t<<<dim3(DMODEL / 32, DMODEL / 32), wblk>>>(w_out, p_wh, p_wl8, p_wh8, DMODEL);
    gemm_mma<<<dim3(DMODEL / BN, MR / BM), blk, GEMM_SMEM>>>(
        p_xh, p_xl8, p_xh8, p_wh, p_wl8, p_wh8, b_out, out, DMODEL,
        0, qn_w, kn_w);
}

// round 8
// speedup vs baseline: 1.0610x; 1.0610x over previous
#include <cuda_runtime.h>
#include <cuda_bf16.h>
#include <math.h>
#include <stdint.h>

// ---------------------------------------------------------------------------
// Problem constants
// ---------------------------------------------------------------------------
#define B_     4
#define NTOK   8192
#define MTOK   1024
#define DMODEL 1024
#define H_     16
#define DH     64
#define EPSF   1e-6f
#define NCHUNK 9               // 9216 / 1024

// ---------------------------------------------------------------------------
// Scratch (static device globals; no allocation allowed)
// ---------------------------------------------------------------------------
__device__ float g_qkv [(size_t)B_ * NTOK * 3 * DMODEL];
__device__ float g_ckv [(size_t)B_ * MTOK * 2 * DMODEL];
__device__ float g_kvp [(size_t)NCHUNK * 64 * DH * DH];
__device__ float g_ksp [(size_t)NCHUNK * 64 * DH];
__device__ float g_kv  [64 * DH * DH];
__device__ float g_ksum[64 * DH];
// bf16 hi/lo split buffers; weights hold qkv(3M) + ckv(2M) + out(1M) = 6M elems
__device__ __nv_bfloat16 g_ah [(size_t)B_ * NTOK * DMODEL];
__device__ __nv_bfloat16 g_al [(size_t)B_ * NTOK * DMODEL];
__device__ __nv_bfloat16 g_yh [(size_t)B_ * MTOK * DMODEL];
__device__ __nv_bfloat16 g_yl [(size_t)B_ * MTOK * DMODEL];
__device__ __nv_bfloat16 g_wh [(size_t)6 * DMODEL * DMODEL];
__device__ __nv_bfloat16 g_wl [(size_t)6 * DMODEL * DMODEL];

// ---------------------------------------------------------------------------
// PTX helpers (sm_80-compatible: cp.async, ldmatrix, mma.sync)
// ---------------------------------------------------------------------------
__device__ __forceinline__ uint32_t smem_u32(const void* p) {
    uint32_t a;
    asm("{ .reg .u64 t; cvta.to.shared.u64 t, %1; cvt.u32.u64 %0, t; }"
        : "=r"(a) : "l"(p));
    return a;
}
__device__ __forceinline__ void cp16(uint32_t s, const void* g) {
    asm volatile("cp.async.cg.shared.global [%0], [%1], 16;" :: "r"(s), "l"(g));
}
#define CP_COMMIT() asm volatile("cp.async.commit_group;" ::: "memory")
#define CP_WAIT1()  asm volatile("cp.async.wait_group 1;" ::: "memory")
#define CP_WAIT0()  asm volatile("cp.async.wait_group 0;" ::: "memory")

__device__ __forceinline__ void ldsm_x4(uint32_t& r0, uint32_t& r1,
                                        uint32_t& r2, uint32_t& r3, uint32_t addr) {
    asm volatile("ldmatrix.sync.aligned.m8n8.x4.shared.b16 {%0,%1,%2,%3}, [%4];"
                 : "=r"(r0), "=r"(r1), "=r"(r2), "=r"(r3) : "r"(addr));
}
__device__ __forceinline__ void mma16816(float* c, const uint32_t* a, const uint32_t* b) {
    asm volatile(
        "mma.sync.aligned.m16n8k16.row.col.f32.bf16.bf16.f32 "
        "{%0,%1,%2,%3}, {%4,%5,%6,%7}, {%8,%9}, {%0,%1,%2,%3};"
        : "+f"(c[0]), "+f"(c[1]), "+f"(c[2]), "+f"(c[3])
        : "r"(a[0]), "r"(a[1]), "r"(a[2]), "r"(a[3]), "r"(b[0]), "r"(b[1]));
}

// ---------------------------------------------------------------------------
// Split fp32 -> bf16 hi + bf16 lo (elementwise, float4 per thread)
// ---------------------------------------------------------------------------
__global__ void __launch_bounds__(256) conv_split(
    const float* __restrict__ in, __nv_bfloat16* __restrict__ hi,
    __nv_bfloat16* __restrict__ lo, int n4)
{
    const int i = blockIdx.x * blockDim.x + threadIdx.x;
    if (i >= n4) return;
    const float4 v = reinterpret_cast<const float4*>(in)[i];
    const __nv_bfloat16 h0 = __float2bfloat16(v.x);
    const __nv_bfloat16 h1 = __float2bfloat16(v.y);
    const __nv_bfloat16 h2 = __float2bfloat16(v.z);
    const __nv_bfloat16 h3 = __float2bfloat16(v.w);
    const __nv_bfloat16 l0 = __float2bfloat16(v.x - __bfloat162float(h0));
    const __nv_bfloat16 l1 = __float2bfloat16(v.y - __bfloat162float(h1));
    const __nv_bfloat16 l2 = __float2bfloat16(v.z - __bfloat162float(h2));
    const __nv_bfloat16 l3 = __float2bfloat16(v.w - __bfloat162float(h3));
    reinterpret_cast<__nv_bfloat162*>(hi)[2 * i]     = __halves2bfloat162(h0, h1);
    reinterpret_cast<__nv_bfloat162*>(hi)[2 * i + 1] = __halves2bfloat162(h2, h3);
    reinterpret_cast<__nv_bfloat162*>(lo)[2 * i]     = __halves2bfloat162(l0, l1);
    reinterpret_cast<__nv_bfloat162*>(lo)[2 * i + 1] = __halves2bfloat162(l2, l3);
}

// ---------------------------------------------------------------------------
// Transpose + split weights: w[1024, C] fp32 -> th/tl[C, 1024] bf16
// ---------------------------------------------------------------------------
__global__ void __launch_bounds__(256) conv_w_t(
    const float* __restrict__ w, __nv_bfloat16* __restrict__ th,
    __nv_bfloat16* __restrict__ tl, int C)
{
    __shared__ float s[32][33];
    const int c0 = blockIdx.x * 32;
    const int k0 = blockIdx.y * 32;
    const int tx = threadIdx.x;
    const int ty = threadIdx.y;
#pragma unroll
    for (int i = 0; i < 32; i += 8)
        s[ty + i][tx] = w[(size_t)(k0 + ty + i) * C + c0 + tx];
    __syncthreads();
#pragma unroll
    for (int i = 0; i < 32; i += 8) {
        const float v = s[tx][ty + i];
        const __nv_bfloat16 h = __float2bfloat16(v);
        const __nv_bfloat16 l = __float2bfloat16(v - __bfloat162float(h));
        const size_t o = (size_t)(c0 + ty + i) * DMODEL + k0 + tx;
        th[o] = h;
        tl[o] = l;
    }
}

// ---------------------------------------------------------------------------
// Split-bf16 tensor-core GEMM via mma.sync (HMMA) with FUSED RMSNorm+ReLU.
//   C[M,Nd] = A[M,1024] @ Bt[Nd,1024]^T + bias (norm for n0 < nlimit)
// 128x128 tile, BK=64 (halved barrier count), 256 threads (8 warps 2x4),
// warp tile 64x32, cp.async double buffer, 144B-padded rows, 3 passes.
// ---------------------------------------------------------------------------
#define BM  128
#define BN  128
#define ROWB 144                      // 128B data + 16B pad (4-bank row shift)
#define TILE_B (128 * ROWB)           // 18432
#define OFF_AH 0
#define OFF_AL TILE_B
#define OFF_BH (2 * TILE_B)
#define OFF_BL (3 * TILE_B)
#define STAGE  (4 * TILE_B)           // 73728
#define GEMM_SMEM (2 * STAGE)         // 147456 (epi needs 68608)
#define CSTRIDE 132

__global__ void __launch_bounds__(256, 1) gemm_mma(
    const __nv_bfloat16* __restrict__ Ah, const __nv_bfloat16* __restrict__ Al,
    const __nv_bfloat16* __restrict__ Bh, const __nv_bfloat16* __restrict__ Bl,
    const float* __restrict__ bias, float* __restrict__ C, int Nd,
    int nlimit, const float* __restrict__ wq, const float* __restrict__ wk)
{
    extern __shared__ char smem[];
    const uint32_t sb = smem_u32(smem);
    const int tid  = threadIdx.x;
    const int wid  = tid >> 5;
    const int lane = tid & 31;
    const int m0 = blockIdx.y * BM;
    const int n0 = blockIdx.x * BN;

    const __nv_bfloat16* gAh = Ah + (size_t)m0 * 1024;
    const __nv_bfloat16* gAl = Al + (size_t)m0 * 1024;
    const __nv_bfloat16* gBh = Bh + (size_t)n0 * 1024;
    const __nv_bfloat16* gBl = Bl + (size_t)n0 * 1024;

    const int lr = tid >> 1;          // row 0..127
    const int hc = (tid & 1) * 64;    // 64B half of the 128B row

    auto load_tile = [&](int buf, int kt) {
        const uint32_t s = sb + buf * STAGE + lr * ROWB + hc;
        const size_t go = (size_t)lr * 1024 + kt * 64 + (hc >> 1);  // bf16 elems
#pragma unroll
        for (int c = 0; c < 4; c++) {
            cp16(s + OFF_AH + c * 16, gAh + go + c * 8);
            cp16(s + OFF_AL + c * 16, gAl + go + c * 8);
            cp16(s + OFF_BH + c * 16, gBh + go + c * 8);
            cp16(s + OFF_BL + c * 16, gBl + go + c * 8);
        }
    };

    const int mbase = (wid >> 2) * 64;
    const int nbase = (wid & 3) * 32;
    const int aRow = mbase + (lane & 15);
    const int aCol = (lane >> 4) * 16;
    const int bRow = nbase + ((lane >> 4) << 3) + (lane & 7);
    const int bCol = ((lane >> 3) & 1) * 16;

    float acc[4][4][4];
#pragma unroll
    for (int i = 0; i < 4; i++)
#pragma unroll
        for (int j = 0; j < 4; j++)
#pragma unroll
            for (int k = 0; k < 4; k++) acc[i][j][k] = 0.0f;

    load_tile(0, 0); CP_COMMIT();
    load_tile(1, 1); CP_COMMIT();

    for (int kt = 0; kt < 16; kt++) {
        if (kt < 15) { CP_WAIT1(); } else { CP_WAIT0(); }
        __syncthreads();
        const uint32_t base = sb + (kt & 1) * STAGE;

#pragma unroll
        for (int ks = 0; ks < 4; ks++) {
            uint32_t ah[4][4], al[4][4], bh[4][2], bl[4][2];
#pragma unroll
            for (int mt = 0; mt < 4; mt++) {
                const uint32_t ad = base + OFF_AH + (aRow + mt * 16) * ROWB + ks * 32 + aCol;
                ldsm_x4(ah[mt][0], ah[mt][1], ah[mt][2], ah[mt][3], ad);
                ldsm_x4(al[mt][0], al[mt][1], al[mt][2], al[mt][3], ad + (OFF_AL - OFF_AH));
            }
#pragma unroll
            for (int p = 0; p < 2; p++) {
                const uint32_t bd = base + OFF_BH + (bRow + p * 16) * ROWB + ks * 32 + bCol;
                uint32_t t0, t1, t2, t3;
                ldsm_x4(t0, t1, t2, t3, bd);
                bh[p * 2][0] = t0; bh[p * 2][1] = t1;
                bh[p * 2 + 1][0] = t2; bh[p * 2 + 1][1] = t3;
                ldsm_x4(t0, t1, t2, t3, bd + (OFF_BL - OFF_BH));
                bl[p * 2][0] = t0; bl[p * 2][1] = t1;
                bl[p * 2 + 1][0] = t2; bl[p * 2 + 1][1] = t3;
            }
#pragma unroll
            for (int mt = 0; mt < 4; mt++)
#pragma unroll
                for (int nt = 0; nt < 4; nt++) {
                    mma16816(acc[mt][nt], ah[mt], bh[nt]);
                    mma16816(acc[mt][nt], ah[mt], bl[nt]);
                    mma16816(acc[mt][nt], al[mt], bh[nt]);
                }
        }
        __syncthreads();
        if (kt + 2 < 16) { load_tile(kt & 1, kt + 2); CP_COMMIT(); }
    }

    // ---- Epilogue: stage (acc+bias) to smem, fused RMSNorm+ReLU, store ----
    __syncthreads();
    float* cs = (float*)smem;
    float* sc = cs + 128 * CSTRIDE;
    {
        const int erow = lane >> 2;
        const int ecol = (lane & 3) * 2;
#pragma unroll
        for (int nt = 0; nt < 4; nt++) {
            const int col = nbase + nt * 8 + ecol;
            const float bx = bias[n0 + col], by = bias[n0 + col + 1];
#pragma unroll
            for (int mt = 0; mt < 4; mt++) {
                const int r0 = mbase + mt * 16 + erow;
                cs[r0 * CSTRIDE + col]           = acc[mt][nt][0] + bx;
                cs[r0 * CSTRIDE + col + 1]       = acc[mt][nt][1] + by;
                cs[(r0 + 8) * CSTRIDE + col]     = acc[mt][nt][2] + bx;
                cs[(r0 + 8) * CSTRIDE + col + 1] = acc[mt][nt][3] + by;
            }
        }
    }
    __syncthreads();

    const bool donorm = (n0 < nlimit);
    if (donorm) {
        const int row  = tid >> 1;
        const int head = tid & 1;
        const float* rp = cs + row * CSTRIDE + head * 64;
        float ss = 0.0f;
#pragma unroll
        for (int j = 0; j < 64; j += 4) {
            float4 v = *(const float4*)(rp + j);
            ss += v.x * v.x + v.y * v.y + v.z * v.z + v.w * v.w;
        }
        sc[tid] = rsqrtf(ss * (1.0f / 64.0f) + EPSF);
        __syncthreads();
    }

    const float* wv = (n0 < 1024) ? wq : wk;
#pragma unroll
    for (int i = 0; i < 16; i++) {
        const int idx = i * 256 + tid;
        const int row = idx >> 5;
        const int c4  = (idx & 31) * 4;
        float4 v = *(float4*)(cs + row * CSTRIDE + c4);
        if (donorm) {
            const float s = sc[row * 2 + (c4 >> 6)];
            const float4 w4 = *(const float4*)(wv + (c4 & 63));
            v.x = fmaxf(v.x * s * w4.x, 0.0f);
            v.y = fmaxf(v.y * s * w4.y, 0.0f);
            v.z = fmaxf(v.z * s * w4.z, 0.0f);
            v.w = fmaxf(v.w * s * w4.w, 0.0f);
        }
        *(float4*)(C + (size_t)(m0 + row) * Nd + n0 + c4) = v;
    }
}

// ---------------------------------------------------------------------------
// kv[b,h,d,e] = sum_s k[s,d] v[s,e];  ksum[b,h,d] = sum_s k[s,d]
// ---------------------------------------------------------------------------
#define SCHUNK 1024
#define SSUB   16

__global__ void kv_accum(const float* __restrict__ qkv, const float* __restrict__ ckv,
                         float* __restrict__ kvp, float* __restrict__ ksp)
{
    const int bh = blockIdx.y;
    const int b  = bh >> 4;
    const int h  = bh & 15;
    const int s0 = blockIdx.x * SCHUNK;

    __shared__ float sk[SSUB][DH];
    __shared__ float sv[SSUB][DH];

    const int tid = threadIdx.x;
    const int d   = tid >> 2;
    const int eg  = tid & 3;

    float acc[16];
#pragma unroll
    for (int j = 0; j < 16; j++) acc[j] = 0.0f;
    float ksl = 0.0f;

    for (int st = s0; st < s0 + SCHUNK; st += SSUB) {
        for (int i = tid; i < SSUB * DH; i += 256) {
            const int si = i >> 6;
            const int dd = i & 63;
            const int s  = st + si;
            float kvvk, kvvv;
            if (s < NTOK) {
                const float* row = qkv + (size_t)(b * NTOK + s) * (3 * DMODEL);
                kvvk = row[DMODEL + h * DH + dd];
                kvvv = row[2 * DMODEL + h * DH + dd];
            } else {
                const float* row = ckv + (size_t)(b * MTOK + (s - NTOK)) * (2 * DMODEL);
                kvvk = row[h * DH + dd];
                kvvv = row[DMODEL + h * DH + dd];
            }
            sk[si][dd] = kvvk;
            sv[si][dd] = kvvv;
        }
        __syncthreads();
#pragma unroll
        for (int si = 0; si < SSUB; si++) {
            const float kd = sk[si][d];
            if (eg == 0) ksl += kd;
#pragma unroll
            for (int j = 0; j < 16; j++)
                acc[j] = fmaf(kd, sv[si][eg * 16 + j], acc[j]);
        }
        __syncthreads();
    }

    float* kvpp = kvp + (size_t)blockIdx.x * 64 * DH * DH + (size_t)bh * DH * DH + d * DH + eg * 16;
#pragma unroll
    for (int j = 0; j < 16; j++) kvpp[j] = acc[j];
    if (eg == 0) ksp[(size_t)blockIdx.x * 64 * DH + bh * DH + d] = ksl;
}

__global__ void kv_reduce(const float* __restrict__ kvp, const float* __restrict__ ksp,
                          float* __restrict__ kv, float* __restrict__ ksum)
{
    const int idx = blockIdx.x * blockDim.x + threadIdx.x;
    if (idx < 64 * DH * DH) {
        float s = 0.0f;
#pragma unroll
        for (int c = 0; c < NCHUNK; c++) s += kvp[(size_t)c * 64 * DH * DH + idx];
        kv[idx] = s;
    }
    if (idx < 64 * DH) {
        float s = 0.0f;
#pragma unroll
        for (int c = 0; c < NCHUNK; c++) s += ksp[(size_t)c * 64 * DH + idx];
        ksum[idx] = s;
    }
}

// ---------------------------------------------------------------------------
// attn = (q @ kv) / (q . ksum + eps); writes hi/lo bf16 split DIRECTLY
// ---------------------------------------------------------------------------
__global__ void attn_apply(const float* __restrict__ qkv, const float* __restrict__ kv,
                           const float* __restrict__ ksum,
                           __nv_bfloat16* __restrict__ oh, __nv_bfloat16* __restrict__ ol)
{
    const int bh = blockIdx.y;
    const int b  = bh >> 4;
    const int h  = bh & 15;

    __shared__ float skv[DH * DH];
    __shared__ float sks[DH];

    const int tid = threadIdx.x;
    for (int i = tid; i < DH * DH; i += 256) skv[i] = kv[(size_t)bh * DH * DH + i];
    if (tid < DH) sks[tid] = ksum[bh * DH + tid];
    __syncthreads();

    const int warp = tid >> 5;
    const int lane = tid & 31;
    const int t0   = blockIdx.x * 64 + warp * 8;

    for (int i = 0; i < 8; i++) {
        const int t = t0 + i;
        const float* qp = qkv + (size_t)(b * NTOK + t) * (3 * DMODEL) + h * DH;
        const float q0 = qp[lane];
        const float q1 = qp[lane + 32];

        float sc = q0 * sks[lane] + q1 * sks[lane + 32];
#pragma unroll
        for (int o = 16; o > 0; o >>= 1) sc += __shfl_xor_sync(0xffffffffu, sc, o);
        const float inv = 1.0f / (sc + EPSF);

        float a0 = 0.0f, a1 = 0.0f;
#pragma unroll
        for (int d = 0; d < 32; d++) {
            const float qd = __shfl_sync(0xffffffffu, q0, d);
            a0 = fmaf(qd, skv[d * DH + lane], a0);
            a1 = fmaf(qd, skv[d * DH + lane + 32], a1);
        }
#pragma unroll
        for (int d = 0; d < 32; d++) {
            const float qd = __shfl_sync(0xffffffffu, q1, d);
            a0 = fmaf(qd, skv[(d + 32) * DH + lane], a0);
            a1 = fmaf(qd, skv[(d + 32) * DH + lane + 32], a1);
        }
        a0 *= inv;
        a1 *= inv;

        const size_t o0 = (size_t)(b * NTOK + t) * DMODEL + h * DH;
        const __nv_bfloat16 h0 = __float2bfloat16(a0);
        const __nv_bfloat16 h1 = __float2bfloat16(a1);
        oh[o0 + lane]      = h0;
        oh[o0 + lane + 32] = h1;
        ol[o0 + lane]      = __float2bfloat16(a0 - __bfloat162float(h0));
        ol[o0 + lane + 32] = __float2bfloat16(a1 - __bfloat162float(h1));
    }
}

// ---------------------------------------------------------------------------
// Launch — weight conversions hoisted so launch #5 (ncu -s 5 -c 1) = QKV GEMM
// ---------------------------------------------------------------------------
extern "C" void kernel_launch(void* const* d_in, const int* in_sizes, int n_in,
                              void* d_out, int out_size)
{
    const float* x     = (const float*)d_in[0];
    const float* y     = (const float*)d_in[1];
    const float* w_qkv = (const float*)d_in[2];
    const float* b_qkv = (const float*)d_in[3];
    const float* w_ckv = (const float*)d_in[4];
    const float* b_ckv = (const float*)d_in[5];
    const float* w_out = (const float*)d_in[6];
    const float* b_out = (const float*)d_in[7];
    const float* qn_w  = (const float*)d_in[8];
    const float* kn_w  = (const float*)d_in[9];
    const float* ckn_w = (const float*)d_in[10];
    float* out = (float*)d_out;

    float *p_qkv, *p_ckv, *p_kvp, *p_ksp, *p_kv, *p_ksum;
    __nv_bfloat16 *p_ah, *p_al, *p_yh, *p_yl, *p_wh, *p_wl;
    cudaGetSymbolAddress((void**)&p_qkv,  g_qkv);
    cudaGetSymbolAddress((void**)&p_ckv,  g_ckv);
    cudaGetSymbolAddress((void**)&p_kvp,  g_kvp);
    cudaGetSymbolAddress((void**)&p_ksp,  g_ksp);
    cudaGetSymbolAddress((void**)&p_kv,   g_kv);
    cudaGetSymbolAddress((void**)&p_ksum, g_ksum);
    cudaGetSymbolAddress((void**)&p_ah,   g_ah);
    cudaGetSymbolAddress((void**)&p_al,   g_al);
    cudaGetSymbolAddress((void**)&p_yh,   g_yh);
    cudaGetSymbolAddress((void**)&p_yl,   g_yl);
    cudaGetSymbolAddress((void**)&p_wh,   g_wh);
    cudaGetSymbolAddress((void**)&p_wl,   g_wl);

    // weight regions: [0,3M) qkv, [3M,5M) ckv, [5M,6M) out
    const size_t W_QKV = 0;
    const size_t W_CKV = (size_t)3 * DMODEL * DMODEL;
    const size_t W_OUT = (size_t)5 * DMODEL * DMODEL;

    cudaFuncSetAttribute(gemm_mma, cudaFuncAttributeMaxDynamicSharedMemorySize, GEMM_SMEM);

    const dim3 blk(256);
    const dim3 wblk(32, 8);
    const int MR = B_ * NTOK;   // 32768
    const int YR = B_ * MTOK;   // 4096

    // [0..2] weight conversions, [3..4] activation splits
    conv_w_t<<<dim3(3 * DMODEL / 32, DMODEL / 32), wblk>>>(w_qkv, p_wh + W_QKV, p_wl + W_QKV, 3 * DMODEL);
    conv_w_t<<<dim3(2 * DMODEL / 32, DMODEL / 32), wblk>>>(w_ckv, p_wh + W_CKV, p_wl + W_CKV, 2 * DMODEL);
    conv_w_t<<<dim3(DMODEL / 32, DMODEL / 32), wblk>>>(w_out, p_wh + W_OUT, p_wl + W_OUT, DMODEL);
    conv_split<<<(MR * DMODEL / 4 + 255) / 256, blk>>>(x, p_ah, p_al, MR * DMODEL / 4);
    conv_split<<<(YR * DMODEL / 4 + 255) / 256, blk>>>(y, p_yh, p_yl, YR * DMODEL / 4);

    // [5] QKV GEMM (ncu capture target) with fused q/k RMSNorm+ReLU
    gemm_mma<<<dim3(3 * DMODEL / BN, MR / BM), blk, GEMM_SMEM>>>(
        p_ah, p_al, p_wh + W_QKV, p_wl + W_QKV, b_qkv, p_qkv, 3 * DMODEL,
        2048, qn_w, kn_w);

    // [6] CKV GEMM with fused c_k RMSNorm+ReLU
    gemm_mma<<<dim3(2 * DMODEL / BN, YR / BM), blk, GEMM_SMEM>>>(
        p_yh, p_yl, p_wh + W_CKV, p_wl + W_CKV, b_ckv, p_ckv, 2 * DMODEL,
        1024, ckn_w, ckn_w);

    // [7..8] kv + k_sum
    kv_accum<<<dim3(NCHUNK, 64), blk>>>(p_qkv, p_ckv, p_kvp, p_ksp);
    kv_reduce<<<(64 * DH * DH + 255) / 256, blk>>>(p_kvp, p_ksp, p_kv, p_ksum);

    // [9] attn (writes bf16 hi/lo split directly into x-side buffers)
    attn_apply<<<dim3(NTOK / 64, 64), blk>>>(p_qkv, p_kv, p_ksum, p_ah, p_al);

    // [10] output GEMM (no norm)
    gemm_mma<<<dim3(DMODEL / BN, MR / BM), blk, GEMM_SMEM>>>(
        p_ah, p_al, p_wh + W_OUT, p_wl + W_OUT, b_out, out, DMODEL,
        0, qn_w, kn_w);
}

// round 9
// speedup vs baseline: 1.5566x; 1.4671x over previous
#include <cuda_runtime.h>
#include <cuda_fp16.h>
#include <math.h>
#include <stdint.h>

// ---------------------------------------------------------------------------
// Problem constants
// ---------------------------------------------------------------------------
#define B_     4
#define NTOK   8192
#define MTOK   1024
#define DMODEL 1024
#define H_     16
#define DH     64
#define EPSF   1e-6f
#define NCHUNK 9               // 9216 / 1024

// ---------------------------------------------------------------------------
// Scratch (static device globals; no allocation allowed)
// ---------------------------------------------------------------------------
__device__ float g_qkv [(size_t)B_ * NTOK * 3 * DMODEL];
__device__ float g_ckv [(size_t)B_ * MTOK * 2 * DMODEL];
__device__ float g_kvp [(size_t)NCHUNK * 64 * DH * DH];
__device__ float g_ksp [(size_t)NCHUNK * 64 * DH];
__device__ float g_kv  [64 * DH * DH];
__device__ float g_ksum[64 * DH];
// fp16 split buffers: A = hi + lo (exact), B = fp16 only
__device__ __half g_ah [(size_t)B_ * NTOK * DMODEL];
__device__ __half g_al [(size_t)B_ * NTOK * DMODEL];
__device__ __half g_yh [(size_t)B_ * MTOK * DMODEL];
__device__ __half g_yl [(size_t)B_ * MTOK * DMODEL];
__device__ __half g_wh [(size_t)6 * DMODEL * DMODEL];  // qkv(3M)+ckv(2M)+out(1M)

// ---------------------------------------------------------------------------
// PTX helpers (sm_80-compatible: cp.async, ldmatrix, mma.sync)
// ---------------------------------------------------------------------------
__device__ __forceinline__ uint32_t smem_u32(const void* p) {
    uint32_t a;
    asm("{ .reg .u64 t; cvta.to.shared.u64 t, %1; cvt.u32.u64 %0, t; }"
        : "=r"(a) : "l"(p));
    return a;
}
__device__ __forceinline__ void cp16(uint32_t s, const void* g) {
    asm volatile("cp.async.cg.shared.global [%0], [%1], 16;" :: "r"(s), "l"(g));
}
#define CP_COMMIT() asm volatile("cp.async.commit_group;" ::: "memory")
#define CP_WAIT1()  asm volatile("cp.async.wait_group 1;" ::: "memory")
#define CP_WAIT0()  asm volatile("cp.async.wait_group 0;" ::: "memory")

__device__ __forceinline__ void ldsm_x4(uint32_t& r0, uint32_t& r1,
                                        uint32_t& r2, uint32_t& r3, uint32_t addr) {
    asm volatile("ldmatrix.sync.aligned.m8n8.x4.shared.b16 {%0,%1,%2,%3}, [%4];"
                 : "=r"(r0), "=r"(r1), "=r"(r2), "=r"(r3) : "r"(addr));
}
__device__ __forceinline__ void mma_f16(float* c, const uint32_t* a, const uint32_t* b) {
    asm volatile(
        "mma.sync.aligned.m16n8k16.row.col.f32.f16.f16.f32 "
        "{%0,%1,%2,%3}, {%4,%5,%6,%7}, {%8,%9}, {%0,%1,%2,%3};"
        : "+f"(c[0]), "+f"(c[1]), "+f"(c[2]), "+f"(c[3])
        : "r"(a[0]), "r"(a[1]), "r"(a[2]), "r"(a[3]), "r"(b[0]), "r"(b[1]));
}

// ---------------------------------------------------------------------------
// Split fp32 -> fp16 hi + fp16 lo (exact two-term split; float4 per thread)
// ---------------------------------------------------------------------------
__global__ void __launch_bounds__(256) conv_split(
    const float* __restrict__ in, __half* __restrict__ hi,
    __half* __restrict__ lo, int n4)
{
    const int i = blockIdx.x * blockDim.x + threadIdx.x;
    if (i >= n4) return;
    const float4 v = reinterpret_cast<const float4*>(in)[i];
    const __half h0 = __float2half(v.x);
    const __half h1 = __float2half(v.y);
    const __half h2 = __float2half(v.z);
    const __half h3 = __float2half(v.w);
    const __half l0 = __float2half(v.x - __half2float(h0));
    const __half l1 = __float2half(v.y - __half2float(h1));
    const __half l2 = __float2half(v.z - __half2float(h2));
    const __half l3 = __float2half(v.w - __half2float(h3));
    reinterpret_cast<__half2*>(hi)[2 * i]     = __halves2half2(h0, h1);
    reinterpret_cast<__half2*>(hi)[2 * i + 1] = __halves2half2(h2, h3);
    reinterpret_cast<__half2*>(lo)[2 * i]     = __halves2half2(l0, l1);
    reinterpret_cast<__half2*>(lo)[2 * i + 1] = __halves2half2(l2, l3);
}

// ---------------------------------------------------------------------------
// Transpose weights: w[1024, C] fp32 -> t[C, 1024] fp16 (no residue)
// ---------------------------------------------------------------------------
__global__ void __launch_bounds__(256) conv_w_t(
    const float* __restrict__ w, __half* __restrict__ th, int C)
{
    __shared__ float s[32][33];
    const int c0 = blockIdx.x * 32;
    const int k0 = blockIdx.y * 32;
    const int tx = threadIdx.x;
    const int ty = threadIdx.y;
#pragma unroll
    for (int i = 0; i < 32; i += 8)
        s[ty + i][tx] = w[(size_t)(k0 + ty + i) * C + c0 + tx];
    __syncthreads();
#pragma unroll
    for (int i = 0; i < 32; i += 8)
        th[(size_t)(c0 + ty + i) * DMODEL + k0 + tx] = __float2half(s[tx][ty + i]);
}

// ---------------------------------------------------------------------------
// 2-pass fp16 tensor-core GEMM via mma.sync with FUSED RMSNorm+ReLU.
//   C[M,Nd] = (Ah + Al)[M,1024] @ Bh[Nd,1024]^T + bias (norm for n0 < nlimit)
// 128x128 tile, BK=32, 256 threads (8 warps 2x4), warp tile 64x32,
// cp.async double buffer, 80B-padded rows.
// ---------------------------------------------------------------------------
#define BM  128
#define BN  128
#define ROWB 80                       // 64B data + 16B pad
#define OFF_AH 0
#define OFF_AL 10240
#define OFF_BH 20480
#define STAGE 30720
#define GEMM_SMEM 69632               // max(2*STAGE=61440, epi 68608) padded
#define CSTRIDE 132

__global__ void __launch_bounds__(256, 2) gemm_mma(
    const __half* __restrict__ Ah, const __half* __restrict__ Al,
    const __half* __restrict__ Bh,
    const float* __restrict__ bias, float* __restrict__ C, int Nd,
    int nlimit, const float* __restrict__ wq, const float* __restrict__ wk)
{
    extern __shared__ char smem[];
    const uint32_t sb = smem_u32(smem);
    const int tid  = threadIdx.x;
    const int wid  = tid >> 5;
    const int lane = tid & 31;
    const int m0 = blockIdx.y * BM;
    const int n0 = blockIdx.x * BN;

    const __half* gAh = Ah + (size_t)m0 * 1024;
    const __half* gAl = Al + (size_t)m0 * 1024;
    const __half* gBh = Bh + (size_t)n0 * 1024;

    const int lr = tid >> 1;
    const int lc = (tid & 1) * 2;

    auto load_tile = [&](int buf, int kt) {
        const uint32_t s0 = sb + buf * STAGE + lr * ROWB + lc * 16;
        const size_t   go = (size_t)lr * 1024 + kt * 32 + lc * 8;
        cp16(s0 + OFF_AH,      gAh + go);
        cp16(s0 + OFF_AH + 16, gAh + go + 8);
        cp16(s0 + OFF_AL,      gAl + go);
        cp16(s0 + OFF_AL + 16, gAl + go + 8);
        cp16(s0 + OFF_BH,      gBh + go);
        cp16(s0 + OFF_BH + 16, gBh + go + 8);
    };

    const int mbase = (wid >> 2) * 64;
    const int nbase = (wid & 3) * 32;
    const int aRow = mbase + (lane & 15);
    const int aCol = (lane >> 4) * 16;
    const int bRow = nbase + ((lane >> 4) << 3) + (lane & 7);
    const int bCol = ((lane >> 3) & 1) * 16;

    float acc[4][4][4];
#pragma unroll
    for (int i = 0; i < 4; i++)
#pragma unroll
        for (int j = 0; j < 4; j++)
#pragma unroll
            for (int k = 0; k < 4; k++) acc[i][j][k] = 0.0f;

    load_tile(0, 0); CP_COMMIT();
    load_tile(1, 1); CP_COMMIT();

    for (int kt = 0; kt < 32; kt++) {
        if (kt < 31) { CP_WAIT1(); } else { CP_WAIT0(); }
        __syncthreads();
        const uint32_t base = sb + (kt & 1) * STAGE;

#pragma unroll
        for (int ks = 0; ks < 2; ks++) {
            uint32_t ah[4][4], al[4][4], bf[4][2];
#pragma unroll
            for (int mt = 0; mt < 4; mt++) {
                const uint32_t ad = base + OFF_AH + (aRow + mt * 16) * ROWB + ks * 32 + aCol;
                ldsm_x4(ah[mt][0], ah[mt][1], ah[mt][2], ah[mt][3], ad);
                ldsm_x4(al[mt][0], al[mt][1], al[mt][2], al[mt][3], ad + (OFF_AL - OFF_AH));
            }
#pragma unroll
            for (int p = 0; p < 2; p++) {
                const uint32_t bd = base + OFF_BH + (bRow + p * 16) * ROWB + ks * 32 + bCol;
                uint32_t t0, t1, t2, t3;
                ldsm_x4(t0, t1, t2, t3, bd);
                bf[p * 2][0] = t0; bf[p * 2][1] = t1;
                bf[p * 2 + 1][0] = t2; bf[p * 2 + 1][1] = t3;
            }
#pragma unroll
            for (int mt = 0; mt < 4; mt++)
#pragma unroll
                for (int nt = 0; nt < 4; nt++) {
                    mma_f16(acc[mt][nt], ah[mt], bf[nt]);
                    mma_f16(acc[mt][nt], al[mt], bf[nt]);
                }
        }
        __syncthreads();
        if (kt + 2 < 32) { load_tile(kt & 1, kt + 2); CP_COMMIT(); }
    }

    // ---- Epilogue: stage (acc+bias) to smem, fused RMSNorm+ReLU, store ----
    __syncthreads();
    float* cs = (float*)smem;
    float* sc = cs + 128 * CSTRIDE;
    {
        const int erow = lane >> 2;
        const int ecol = (lane & 3) * 2;
#pragma unroll
        for (int nt = 0; nt < 4; nt++) {
            const int col = nbase + nt * 8 + ecol;
            const float bx = bias[n0 + col], by = bias[n0 + col + 1];
#pragma unroll
            for (int mt = 0; mt < 4; mt++) {
                const int r0 = mbase + mt * 16 + erow;
                cs[r0 * CSTRIDE + col]           = acc[mt][nt][0] + bx;
                cs[r0 * CSTRIDE + col + 1]       = acc[mt][nt][1] + by;
                cs[(r0 + 8) * CSTRIDE + col]     = acc[mt][nt][2] + bx;
                cs[(r0 + 8) * CSTRIDE + col + 1] = acc[mt][nt][3] + by;
            }
        }
    }
    __syncthreads();

    const bool donorm = (n0 < nlimit);
    if (donorm) {
        const int row  = tid >> 1;
        const int head = tid & 1;
        const float* rp = cs + row * CSTRIDE + head * 64;
        float ss = 0.0f;
#pragma unroll
        for (int j = 0; j < 64; j += 4) {
            float4 v = *(const float4*)(rp + j);
            ss += v.x * v.x + v.y * v.y + v.z * v.z + v.w * v.w;
        }
        sc[tid] = rsqrtf(ss * (1.0f / 64.0f) + EPSF);
        __syncthreads();
    }

    const float* wv = (n0 < 1024) ? wq : wk;
#pragma unroll
    for (int i = 0; i < 16; i++) {
        const int idx = i * 256 + tid;
        const int row = idx >> 5;
        const int c4  = (idx & 31) * 4;
        float4 v = *(float4*)(cs + row * CSTRIDE + c4);
        if (donorm) {
            const float s = sc[row * 2 + (c4 >> 6)];
            const float4 w4 = *(const float4*)(wv + (c4 & 63));
            v.x = fmaxf(v.x * s * w4.x, 0.0f);
            v.y = fmaxf(v.y * s * w4.y, 0.0f);
            v.z = fmaxf(v.z * s * w4.z, 0.0f);
            v.w = fmaxf(v.w * s * w4.w, 0.0f);
        }
        *(float4*)(C + (size_t)(m0 + row) * Nd + n0 + c4) = v;
    }
}

// ---------------------------------------------------------------------------
// kv[b,h,d,e] = sum_s k[s,d] v[s,e];  ksum[b,h,d] = sum_s k[s,d]
// ---------------------------------------------------------------------------
#define SCHUNK 1024
#define SSUB   16

__global__ void kv_accum(const float* __restrict__ qkv, const float* __restrict__ ckv,
                         float* __restrict__ kvp, float* __restrict__ ksp)
{
    const int bh = blockIdx.y;
    const int b  = bh >> 4;
    const int h  = bh & 15;
    const int s0 = blockIdx.x * SCHUNK;

    __shared__ float sk[SSUB][DH];
    __shared__ float sv[SSUB][DH];

    const int tid = threadIdx.x;
    const int d   = tid >> 2;
    const int eg  = tid & 3;

    float acc[16];
#pragma unroll
    for (int j = 0; j < 16; j++) acc[j] = 0.0f;
    float ksl = 0.0f;

    for (int st = s0; st < s0 + SCHUNK; st += SSUB) {
        for (int i = tid; i < SSUB * DH; i += 256) {
            const int si = i >> 6;
            const int dd = i & 63;
            const int s  = st + si;
            float kvvk, kvvv;
            if (s < NTOK) {
                const float* row = qkv + (size_t)(b * NTOK + s) * (3 * DMODEL);
                kvvk = row[DMODEL + h * DH + dd];
                kvvv = row[2 * DMODEL + h * DH + dd];
            } else {
                const float* row = ckv + (size_t)(b * MTOK + (s - NTOK)) * (2 * DMODEL);
                kvvk = row[h * DH + dd];
                kvvv = row[DMODEL + h * DH + dd];
            }
            sk[si][dd] = kvvk;
            sv[si][dd] = kvvv;
        }
        __syncthreads();
#pragma unroll
        for (int si = 0; si < SSUB; si++) {
            const float kd = sk[si][d];
            if (eg == 0) ksl += kd;
#pragma unroll
            for (int j = 0; j < 16; j++)
                acc[j] = fmaf(kd, sv[si][eg * 16 + j], acc[j]);
        }
        __syncthreads();
    }

    float* kvpp = kvp + (size_t)blockIdx.x * 64 * DH * DH + (size_t)bh * DH * DH + d * DH + eg * 16;
#pragma unroll
    for (int j = 0; j < 16; j++) kvpp[j] = acc[j];
    if (eg == 0) ksp[(size_t)blockIdx.x * 64 * DH + bh * DH + d] = ksl;
}

__global__ void kv_reduce(const float* __restrict__ kvp, const float* __restrict__ ksp,
                          float* __restrict__ kv, float* __restrict__ ksum)
{
    const int idx = blockIdx.x * blockDim.x + threadIdx.x;
    if (idx < 64 * DH * DH) {
        float s = 0.0f;
#pragma unroll
        for (int c = 0; c < NCHUNK; c++) s += kvp[(size_t)c * 64 * DH * DH + idx];
        kv[idx] = s;
    }
    if (idx < 64 * DH) {
        float s = 0.0f;
#pragma unroll
        for (int c = 0; c < NCHUNK; c++) s += ksp[(size_t)c * 64 * DH + idx];
        ksum[idx] = s;
    }
}

// ---------------------------------------------------------------------------
// attn = (q @ kv) / (q . ksum + eps); writes fp16 hi/lo split DIRECTLY
// ---------------------------------------------------------------------------
__global__ void attn_apply(const float* __restrict__ qkv, const float* __restrict__ kv,
                           const float* __restrict__ ksum,
                           __half* __restrict__ oh, __half* __restrict__ ol)
{
    const int bh = blockIdx.y;
    const int b  = bh >> 4;
    const int h  = bh & 15;

    __shared__ float skv[DH * DH];
    __shared__ float sks[DH];

    const int tid = threadIdx.x;
    for (int i = tid; i < DH * DH; i += 256) skv[i] = kv[(size_t)bh * DH * DH + i];
    if (tid < DH) sks[tid] = ksum[bh * DH + tid];
    __syncthreads();

    const int warp = tid >> 5;
    const int lane = tid & 31;
    const int t0   = blockIdx.x * 64 + warp * 8;

    for (int i = 0; i < 8; i++) {
        const int t = t0 + i;
        const float* qp = qkv + (size_t)(b * NTOK + t) * (3 * DMODEL) + h * DH;
        const float q0 = qp[lane];
        const float q1 = qp[lane + 32];

        float sc = q0 * sks[lane] + q1 * sks[lane + 32];
#pragma unroll
        for (int o = 16; o > 0; o >>= 1) sc += __shfl_xor_sync(0xffffffffu, sc, o);
        const float inv = 1.0f / (sc + EPSF);

        float a0 = 0.0f, a1 = 0.0f;
#pragma unroll
        for (int d = 0; d < 32; d++) {
            const float qd = __shfl_sync(0xffffffffu, q0, d);
            a0 = fmaf(qd, skv[d * DH + lane], a0);
            a1 = fmaf(qd, skv[d * DH + lane + 32], a1);
        }
#pragma unroll
        for (int d = 0; d < 32; d++) {
            const float qd = __shfl_sync(0xffffffffu, q1, d);
            a0 = fmaf(qd, skv[(d + 32) * DH + lane], a0);
            a1 = fmaf(qd, skv[(d + 32) * DH + lane + 32], a1);
        }
        a0 *= inv;
        a1 *= inv;

        const size_t o0 = (size_t)(b * NTOK + t) * DMODEL + h * DH;
        const __half h0 = __float2half(a0);
        const __half h1 = __float2half(a1);
        oh[o0 + lane]      = h0;
        oh[o0 + lane + 32] = h1;
        ol[o0 + lane]      = __float2half(a0 - __half2float(h0));
        ol[o0 + lane + 32] = __float2half(a1 - __half2float(h1));
    }
}

// ---------------------------------------------------------------------------
// Launch
// ---------------------------------------------------------------------------
extern "C" void kernel_launch(void* const* d_in, const int* in_sizes, int n_in,
                              void* d_out, int out_size)
{
    const float* x     = (const float*)d_in[0];
    const float* y     = (const float*)d_in[1];
    const float* w_qkv = (const float*)d_in[2];
    const float* b_qkv = (const float*)d_in[3];
    const float* w_ckv = (const float*)d_in[4];
    const float* b_ckv = (const float*)d_in[5];
    const float* w_out = (const float*)d_in[6];
    const float* b_out = (const float*)d_in[7];
    const float* qn_w  = (const float*)d_in[8];
    const float* kn_w  = (const float*)d_in[9];
    const float* ckn_w = (const float*)d_in[10];
    float* out = (float*)d_out;

    float *p_qkv, *p_ckv, *p_kvp, *p_ksp, *p_kv, *p_ksum;
    __half *p_ah, *p_al, *p_yh, *p_yl, *p_wh;
    cudaGetSymbolAddress((void**)&p_qkv,  g_qkv);
    cudaGetSymbolAddress((void**)&p_ckv,  g_ckv);
    cudaGetSymbolAddress((void**)&p_kvp,  g_kvp);
    cudaGetSymbolAddress((void**)&p_ksp,  g_ksp);
    cudaGetSymbolAddress((void**)&p_kv,   g_kv);
    cudaGetSymbolAddress((void**)&p_ksum, g_ksum);
    cudaGetSymbolAddress((void**)&p_ah,   g_ah);
    cudaGetSymbolAddress((void**)&p_al,   g_al);
    cudaGetSymbolAddress((void**)&p_yh,   g_yh);
    cudaGetSymbolAddress((void**)&p_yl,   g_yl);
    cudaGetSymbolAddress((void**)&p_wh,   g_wh);

    // weight regions: [0,3M) qkv, [3M,5M) ckv, [5M,6M) out
    const size_t W_QKV = 0;
    const size_t W_CKV = (size_t)3 * DMODEL * DMODEL;
    const size_t W_OUT = (size_t)5 * DMODEL * DMODEL;

    cudaFuncSetAttribute(gemm_mma, cudaFuncAttributeMaxDynamicSharedMemorySize, GEMM_SMEM);

    const dim3 blk(256);
    const dim3 wblk(32, 8);
    const int MR = B_ * NTOK;   // 32768
    const int YR = B_ * MTOK;   // 4096

    // conversions
    conv_w_t<<<dim3(3 * DMODEL / 32, DMODEL / 32), wblk>>>(w_qkv, p_wh + W_QKV, 3 * DMODEL);
    conv_w_t<<<dim3(2 * DMODEL / 32, DMODEL / 32), wblk>>>(w_ckv, p_wh + W_CKV, 2 * DMODEL);
    conv_w_t<<<dim3(DMODEL / 32, DMODEL / 32), wblk>>>(w_out, p_wh + W_OUT, DMODEL);
    conv_split<<<(MR * DMODEL / 4 + 255) / 256, blk>>>(x, p_ah, p_al, MR * DMODEL / 4);
    conv_split<<<(YR * DMODEL / 4 + 255) / 256, blk>>>(y, p_yh, p_yl, YR * DMODEL / 4);

    // QKV GEMM with fused q/k RMSNorm+ReLU
    gemm_mma<<<dim3(3 * DMODEL / BN, MR / BM), blk, GEMM_SMEM>>>(
        p_ah, p_al, p_wh + W_QKV, b_qkv, p_qkv, 3 * DMODEL, 2048, qn_w, kn_w);

    // CKV GEMM with fused c_k RMSNorm+ReLU
    gemm_mma<<<dim3(2 * DMODEL / BN, YR / BM), blk, GEMM_SMEM>>>(
        p_yh, p_yl, p_wh + W_CKV, b_ckv, p_ckv, 2 * DMODEL, 1024, ckn_w, ckn_w);

    // kv + k_sum
    kv_accum<<<dim3(NCHUNK, 64), blk>>>(p_qkv, p_ckv, p_kvp, p_ksp);
    kv_reduce<<<(64 * DH * DH + 255) / 256, blk>>>(p_kvp, p_ksp, p_kv, p_ksum);

    // attn (writes fp16 hi/lo split directly into x-side buffers)
    attn_apply<<<dim3(NTOK / 64, 64), blk>>>(p_qkv, p_kv, p_ksum, p_ah, p_al);

    // output GEMM (no norm)
    gemm_mma<<<dim3(DMODEL / BN, MR / BM), blk, GEMM_SMEM>>>(
        p_ah, p_al, p_wh + W_OUT, b_out, out, DMODEL, 0, qn_w, kn_w);
}

// round 10
// speedup vs baseline: 2.0542x; 1.3196x over previous
#include <cuda_runtime.h>
#include <cuda_fp16.h>
#include <math.h>
#include <stdint.h>

// ---------------------------------------------------------------------------
// Problem constants
// ---------------------------------------------------------------------------
#define B_     4
#define NTOK   8192
#define MTOK   1024
#define DMODEL 1024
#define H_     16
#define DH     64
#define EPSF   1e-6f
#define NCHUNK 9               // 9216 / 1024

// ---------------------------------------------------------------------------
// Scratch (static device globals; no allocation allowed)
// ---------------------------------------------------------------------------
__device__ float g_qkv [(size_t)B_ * NTOK * 3 * DMODEL];
__device__ float g_ckv [(size_t)B_ * MTOK * 2 * DMODEL];
__device__ float g_kvp [(size_t)NCHUNK * 64 * DH * DH];
__device__ float g_ksp [(size_t)NCHUNK * 64 * DH];
__device__ float g_kv  [64 * DH * DH];
__device__ float g_ksum[64 * DH];
// plain fp16 operand buffers
__device__ __half g_ah [(size_t)B_ * NTOK * DMODEL];
__device__ __half g_yh [(size_t)B_ * MTOK * DMODEL];
__device__ __half g_wh [(size_t)6 * DMODEL * DMODEL];  // qkv(3M)+ckv(2M)+out(1M)

// ---------------------------------------------------------------------------
// PTX helpers (sm_80-compatible: cp.async, ldmatrix, mma.sync)
// ---------------------------------------------------------------------------
__device__ __forceinline__ uint32_t smem_u32(const void* p) {
    uint32_t a;
    asm("{ .reg .u64 t; cvta.to.shared.u64 t, %1; cvt.u32.u64 %0, t; }"
        : "=r"(a) : "l"(p));
    return a;
}
__device__ __forceinline__ void cp16(uint32_t s, const void* g) {
    asm volatile("cp.async.cg.shared.global [%0], [%1], 16;" :: "r"(s), "l"(g));
}
#define CP_COMMIT() asm volatile("cp.async.commit_group;" ::: "memory")
#define CP_WAIT1()  asm volatile("cp.async.wait_group 1;" ::: "memory")
#define CP_WAIT0()  asm volatile("cp.async.wait_group 0;" ::: "memory")

__device__ __forceinline__ void ldsm_x4(uint32_t& r0, uint32_t& r1,
                                        uint32_t& r2, uint32_t& r3, uint32_t addr) {
    asm volatile("ldmatrix.sync.aligned.m8n8.x4.shared.b16 {%0,%1,%2,%3}, [%4];"
                 : "=r"(r0), "=r"(r1), "=r"(r2), "=r"(r3) : "r"(addr));
}
__device__ __forceinline__ void mma_f16(float* c, const uint32_t* a, const uint32_t* b) {
    asm volatile(
        "mma.sync.aligned.m16n8k16.row.col.f32.f16.f16.f32 "
        "{%0,%1,%2,%3}, {%4,%5,%6,%7}, {%8,%9}, {%0,%1,%2,%3};"
        : "+f"(c[0]), "+f"(c[1]), "+f"(c[2]), "+f"(c[3])
        : "r"(a[0]), "r"(a[1]), "r"(a[2]), "r"(a[3]), "r"(b[0]), "r"(b[1]));
}

// ---------------------------------------------------------------------------
// Convert fp32 -> fp16 (elementwise, float4 per thread)
// ---------------------------------------------------------------------------
__global__ void __launch_bounds__(256) conv_h(
    const float* __restrict__ in, __half* __restrict__ hi, int n4)
{
    const int i = blockIdx.x * blockDim.x + threadIdx.x;
    if (i >= n4) return;
    const float4 v = reinterpret_cast<const float4*>(in)[i];
    reinterpret_cast<__half2*>(hi)[2 * i]     = __halves2half2(__float2half(v.x), __float2half(v.y));
    reinterpret_cast<__half2*>(hi)[2 * i + 1] = __halves2half2(__float2half(v.z), __float2half(v.w));
}

// ---------------------------------------------------------------------------
// Transpose weights: w[1024, C] fp32 -> t[C, 1024] fp16
// ---------------------------------------------------------------------------
__global__ void __launch_bounds__(256) conv_w_t(
    const float* __restrict__ w, __half* __restrict__ th, int C)
{
    __shared__ float s[32][33];
    const int c0 = blockIdx.x * 32;
    const int k0 = blockIdx.y * 32;
    const int tx = threadIdx.x;
    const int ty = threadIdx.y;
#pragma unroll
    for (int i = 0; i < 32; i += 8)
        s[ty + i][tx] = w[(size_t)(k0 + ty + i) * C + c0 + tx];
    __syncthreads();
#pragma unroll
    for (int i = 0; i < 32; i += 8)
        th[(size_t)(c0 + ty + i) * DMODEL + k0 + tx] = __float2half(s[tx][ty + i]);
}

// ---------------------------------------------------------------------------
// Single-pass fp16 tensor-core GEMM via mma.sync with FUSED RMSNorm+ReLU.
//   C[M,Nd] = A[M,1024] @ B[Nd,1024]^T + bias (norm for n0 < nlimit)
// 128x128 tile, BK=32, 256 threads (8 warps 2x4), warp tile 64x32,
// cp.async double buffer, 80B-padded rows.
// ---------------------------------------------------------------------------
#define BM  128
#define BN  128
#define ROWB 80                       // 64B data + 16B pad
#define OFF_A 0
#define OFF_B 10240
#define STAGE 20480
#define GEMM_SMEM 69632               // epilogue needs 128*132*4 + 1024 = 68608
#define CSTRIDE 132

__global__ void __launch_bounds__(256, 2) gemm_mma(
    const __half* __restrict__ Ah, const __half* __restrict__ Bh,
    const float* __restrict__ bias, float* __restrict__ C, int Nd,
    int nlimit, const float* __restrict__ wq, const float* __restrict__ wk)
{
    extern __shared__ char smem[];
    const uint32_t sb = smem_u32(smem);
    const int tid  = threadIdx.x;
    const int wid  = tid >> 5;
    const int lane = tid & 31;
    const int m0 = blockIdx.y * BM;
    const int n0 = blockIdx.x * BN;

    const __half* gA = Ah + (size_t)m0 * 1024;
    const __half* gB = Bh + (size_t)n0 * 1024;

    const int lr = tid >> 1;
    const int lc = (tid & 1) * 2;

    auto load_tile = [&](int buf, int kt) {
        const uint32_t s0 = sb + buf * STAGE + lr * ROWB + lc * 16;
        const size_t   go = (size_t)lr * 1024 + kt * 32 + lc * 8;
        cp16(s0 + OFF_A,      gA + go);
        cp16(s0 + OFF_A + 16, gA + go + 8);
        cp16(s0 + OFF_B,      gB + go);
        cp16(s0 + OFF_B + 16, gB + go + 8);
    };

    const int mbase = (wid >> 2) * 64;
    const int nbase = (wid & 3) * 32;
    const int aRow = mbase + (lane & 15);
    const int aCol = (lane >> 4) * 16;
    const int bRow = nbase + ((lane >> 4) << 3) + (lane & 7);
    const int bCol = ((lane >> 3) & 1) * 16;

    float acc[4][4][4];
#pragma unroll
    for (int i = 0; i < 4; i++)
#pragma unroll
        for (int j = 0; j < 4; j++)
#pragma unroll
            for (int k = 0; k < 4; k++) acc[i][j][k] = 0.0f;

    load_tile(0, 0); CP_COMMIT();
    load_tile(1, 1); CP_COMMIT();

    for (int kt = 0; kt < 32; kt++) {
        if (kt < 31) { CP_WAIT1(); } else { CP_WAIT0(); }
        __syncthreads();
        const uint32_t base = sb + (kt & 1) * STAGE;

#pragma unroll
        for (int ks = 0; ks < 2; ks++) {
            uint32_t af[4][4], bf[4][2];
#pragma unroll
            for (int mt = 0; mt < 4; mt++)
                ldsm_x4(af[mt][0], af[mt][1], af[mt][2], af[mt][3],
                        base + OFF_A + (aRow + mt * 16) * ROWB + ks * 32 + aCol);
#pragma unroll
            for (int p = 0; p < 2; p++) {
                uint32_t t0, t1, t2, t3;
                ldsm_x4(t0, t1, t2, t3,
                        base + OFF_B + (bRow + p * 16) * ROWB + ks * 32 + bCol);
                bf[p * 2][0] = t0; bf[p * 2][1] = t1;
                bf[p * 2 + 1][0] = t2; bf[p * 2 + 1][1] = t3;
            }
#pragma unroll
            for (int mt = 0; mt < 4; mt++)
#pragma unroll
                for (int nt = 0; nt < 4; nt++)
                    mma_f16(acc[mt][nt], af[mt], bf[nt]);
        }
        __syncthreads();
        if (kt + 2 < 32) { load_tile(kt & 1, kt + 2); CP_COMMIT(); }
    }

    // ---- Epilogue: stage (acc+bias) to smem, fused RMSNorm+ReLU, store ----
    __syncthreads();
    float* cs = (float*)smem;
    float* sc = cs + 128 * CSTRIDE;
    {
        const int erow = lane >> 2;
        const int ecol = (lane & 3) * 2;
#pragma unroll
        for (int nt = 0; nt < 4; nt++) {
            const int col = nbase + nt * 8 + ecol;
            const float bx = bias[n0 + col], by = bias[n0 + col + 1];
#pragma unroll
            for (int mt = 0; mt < 4; mt++) {
                const int r0 = mbase + mt * 16 + erow;
                cs[r0 * CSTRIDE + col]           = acc[mt][nt][0] + bx;
                cs[r0 * CSTRIDE + col + 1]       = acc[mt][nt][1] + by;
                cs[(r0 + 8) * CSTRIDE + col]     = acc[mt][nt][2] + bx;
                cs[(r0 + 8) * CSTRIDE + col + 1] = acc[mt][nt][3] + by;
            }
        }
    }
    __syncthreads();

    const bool donorm = (n0 < nlimit);
    if (donorm) {
        const int row  = tid >> 1;
        const int head = tid & 1;
        const float* rp = cs + row * CSTRIDE + head * 64;
        float ss = 0.0f;
#pragma unroll
        for (int j = 0; j < 64; j += 4) {
            float4 v = *(const float4*)(rp + j);
            ss += v.x * v.x + v.y * v.y + v.z * v.z + v.w * v.w;
        }
        sc[tid] = rsqrtf(ss * (1.0f / 64.0f) + EPSF);
        __syncthreads();
    }

    const float* wv = (n0 < 1024) ? wq : wk;
#pragma unroll
    for (int i = 0; i < 16; i++) {
        const int idx = i * 256 + tid;
        const int row = idx >> 5;
        const int c4  = (idx & 31) * 4;
        float4 v = *(float4*)(cs + row * CSTRIDE + c4);
        if (donorm) {
            const float s = sc[row * 2 + (c4 >> 6)];
            const float4 w4 = *(const float4*)(wv + (c4 & 63));
            v.x = fmaxf(v.x * s * w4.x, 0.0f);
            v.y = fmaxf(v.y * s * w4.y, 0.0f);
            v.z = fmaxf(v.z * s * w4.z, 0.0f);
            v.w = fmaxf(v.w * s * w4.w, 0.0f);
        }
        *(float4*)(C + (size_t)(m0 + row) * Nd + n0 + c4) = v;
    }
}

// ---------------------------------------------------------------------------
// kv[b,h,d,e] = sum_s k[s,d] v[s,e];  ksum[b,h,d] = sum_s k[s,d]
// ---------------------------------------------------------------------------
#define SCHUNK 1024
#define SSUB   16

__global__ void kv_accum(const float* __restrict__ qkv, const float* __restrict__ ckv,
                         float* __restrict__ kvp, float* __restrict__ ksp)
{
    const int bh = blockIdx.y;
    const int b  = bh >> 4;
    const int h  = bh & 15;
    const int s0 = blockIdx.x * SCHUNK;

    __shared__ float sk[SSUB][DH];
    __shared__ float sv[SSUB][DH];

    const int tid = threadIdx.x;
    const int d   = tid >> 2;
    const int eg  = tid & 3;

    float acc[16];
#pragma unroll
    for (int j = 0; j < 16; j++) acc[j] = 0.0f;
    float ksl = 0.0f;

    for (int st = s0; st < s0 + SCHUNK; st += SSUB) {
        for (int i = tid; i < SSUB * DH; i += 256) {
            const int si = i >> 6;
            const int dd = i & 63;
            const int s  = st + si;
            float kvvk, kvvv;
            if (s < NTOK) {
                const float* row = qkv + (size_t)(b * NTOK + s) * (3 * DMODEL);
                kvvk = row[DMODEL + h * DH + dd];
                kvvv = row[2 * DMODEL + h * DH + dd];
            } else {
                const float* row = ckv + (size_t)(b * MTOK + (s - NTOK)) * (2 * DMODEL);
                kvvk = row[h * DH + dd];
                kvvv = row[DMODEL + h * DH + dd];
            }
            sk[si][dd] = kvvk;
            sv[si][dd] = kvvv;
        }
        __syncthreads();
#pragma unroll
        for (int si = 0; si < SSUB; si++) {
            const float kd = sk[si][d];
            if (eg == 0) ksl += kd;
#pragma unroll
            for (int j = 0; j < 16; j++)
                acc[j] = fmaf(kd, sv[si][eg * 16 + j], acc[j]);
        }
        __syncthreads();
    }

    float* kvpp = kvp + (size_t)blockIdx.x * 64 * DH * DH + (size_t)bh * DH * DH + d * DH + eg * 16;
#pragma unroll
    for (int j = 0; j < 16; j++) kvpp[j] = acc[j];
    if (eg == 0) ksp[(size_t)blockIdx.x * 64 * DH + bh * DH + d] = ksl;
}

__global__ void kv_reduce(const float* __restrict__ kvp, const float* __restrict__ ksp,
                          float* __restrict__ kv, float* __restrict__ ksum)
{
    const int idx = blockIdx.x * blockDim.x + threadIdx.x;
    if (idx < 64 * DH * DH) {
        float s = 0.0f;
#pragma unroll
        for (int c = 0; c < NCHUNK; c++) s += kvp[(size_t)c * 64 * DH * DH + idx];
        kv[idx] = s;
    }
    if (idx < 64 * DH) {
        float s = 0.0f;
#pragma unroll
        for (int c = 0; c < NCHUNK; c++) s += ksp[(size_t)c * 64 * DH + idx];
        ksum[idx] = s;
    }
}

// ---------------------------------------------------------------------------
// attn = (q @ kv) / (q . ksum + eps); writes fp16 directly
// ---------------------------------------------------------------------------
__global__ void attn_apply(const float* __restrict__ qkv, const float* __restrict__ kv,
                           const float* __restrict__ ksum, __half* __restrict__ oh)
{
    const int bh = blockIdx.y;
    const int b  = bh >> 4;
    const int h  = bh & 15;

    __shared__ float skv[DH * DH];
    __shared__ float sks[DH];

    const int tid = threadIdx.x;
    for (int i = tid; i < DH * DH; i += 256) skv[i] = kv[(size_t)bh * DH * DH + i];
    if (tid < DH) sks[tid] = ksum[bh * DH + tid];
    __syncthreads();

    const int warp = tid >> 5;
    const int lane = tid & 31;
    const int t0   = blockIdx.x * 64 + warp * 8;

    for (int i = 0; i < 8; i++) {
        const int t = t0 + i;
        const float* qp = qkv + (size_t)(b * NTOK + t) * (3 * DMODEL) + h * DH;
        const float q0 = qp[lane];
        const float q1 = qp[lane + 32];

        float sc = q0 * sks[lane] + q1 * sks[lane + 32];
#pragma unroll
        for (int o = 16; o > 0; o >>= 1) sc += __shfl_xor_sync(0xffffffffu, sc, o);
        const float inv = 1.0f / (sc + EPSF);

        float a0 = 0.0f, a1 = 0.0f;
#pragma unroll
        for (int d = 0; d < 32; d++) {
            const float qd = __shfl_sync(0xffffffffu, q0, d);
            a0 = fmaf(qd, skv[d * DH + lane], a0);
            a1 = fmaf(qd, skv[d * DH + lane + 32], a1);
        }
#pragma unroll
        for (int d = 0; d < 32; d++) {
            const float qd = __shfl_sync(0xffffffffu, q1, d);
            a0 = fmaf(qd, skv[(d + 32) * DH + lane], a0);
            a1 = fmaf(qd, skv[(d + 32) * DH + lane + 32], a1);
        }

        const size_t o0 = (size_t)(b * NTOK + t) * DMODEL + h * DH;
        oh[o0 + lane]      = __float2half(a0 * inv);
        oh[o0 + lane + 32] = __float2half(a1 * inv);
    }
}

// ---------------------------------------------------------------------------
// Launch
// ---------------------------------------------------------------------------
extern "C" void kernel_launch(void* const* d_in, const int* in_sizes, int n_in,
                              void* d_out, int out_size)
{
    const float* x     = (const float*)d_in[0];
    const float* y     = (const float*)d_in[1];
    const float* w_qkv = (const float*)d_in[2];
    const float* b_qkv = (const float*)d_in[3];
    const float* w_ckv = (const float*)d_in[4];
    const float* b_ckv = (const float*)d_in[5];
    const float* w_out = (const float*)d_in[6];
    const float* b_out = (const float*)d_in[7];
    const float* qn_w  = (const float*)d_in[8];
    const float* kn_w  = (const float*)d_in[9];
    const float* ckn_w = (const float*)d_in[10];
    float* out = (float*)d_out;

    float *p_qkv, *p_ckv, *p_kvp, *p_ksp, *p_kv, *p_ksum;
    __half *p_ah, *p_yh, *p_wh;
    cudaGetSymbolAddress((void**)&p_qkv,  g_qkv);
    cudaGetSymbolAddress((void**)&p_ckv,  g_ckv);
    cudaGetSymbolAddress((void**)&p_kvp,  g_kvp);
    cudaGetSymbolAddress((void**)&p_ksp,  g_ksp);
    cudaGetSymbolAddress((void**)&p_kv,   g_kv);
    cudaGetSymbolAddress((void**)&p_ksum, g_ksum);
    cudaGetSymbolAddress((void**)&p_ah,   g_ah);
    cudaGetSymbolAddress((void**)&p_yh,   g_yh);
    cudaGetSymbolAddress((void**)&p_wh,   g_wh);

    // weight regions: [0,3M) qkv, [3M,5M) ckv, [5M,6M) out
    const size_t W_QKV = 0;
    const size_t W_CKV = (size_t)3 * DMODEL * DMODEL;
    const size_t W_OUT = (size_t)5 * DMODEL * DMODEL;

    cudaFuncSetAttribute(gemm_mma, cudaFuncAttributeMaxDynamicSharedMemorySize, GEMM_SMEM);

    const dim3 blk(256);
    const dim3 wblk(32, 8);
    const int MR = B_ * NTOK;   // 32768
    const int YR = B_ * MTOK;   // 4096

    // conversions
    conv_w_t<<<dim3(3 * DMODEL / 32, DMODEL / 32), wblk>>>(w_qkv, p_wh + W_QKV, 3 * DMODEL);
    conv_w_t<<<dim3(2 * DMODEL / 32, DMODEL / 32), wblk>>>(w_ckv, p_wh + W_CKV, 2 * DMODEL);
    conv_w_t<<<dim3(DMODEL / 32, DMODEL / 32), wblk>>>(w_out, p_wh + W_OUT, DMODEL);
    conv_h<<<(MR * DMODEL / 4 + 255) / 256, blk>>>(x, p_ah, MR * DMODEL / 4);
    conv_h<<<(YR * DMODEL / 4 + 255) / 256, blk>>>(y, p_yh, YR * DMODEL / 4);

    // QKV GEMM with fused q/k RMSNorm+ReLU
    gemm_mma<<<dim3(3 * DMODEL / BN, MR / BM), blk, GEMM_SMEM>>>(
        p_ah, p_wh + W_QKV, b_qkv, p_qkv, 3 * DMODEL, 2048, qn_w, kn_w);

    // CKV GEMM with fused c_k RMSNorm+ReLU
    gemm_mma<<<dim3(2 * DMODEL / BN, YR / BM), blk, GEMM_SMEM>>>(
        p_yh, p_wh + W_CKV, b_ckv, p_ckv, 2 * DMODEL, 1024, ckn_w, ckn_w);

    // kv + k_sum
    kv_accum<<<dim3(NCHUNK, 64), blk>>>(p_qkv, p_ckv, p_kvp, p_ksp);
    kv_reduce<<<(64 * DH * DH + 255) / 256, blk>>>(p_kvp, p_ksp, p_kv, p_ksum);

    // attn (writes fp16 directly into x-side buffer)
    attn_apply<<<dim3(NTOK / 64, 64), blk>>>(p_qkv, p_kv, p_ksum, p_ah);

    // output GEMM (no norm)
    gemm_mma<<<dim3(DMODEL / BN, MR / BM), blk, GEMM_SMEM>>>(
        p_ah, p_wh + W_OUT, b_out, out, DMODEL, 0, qn_w, kn_w);
}

// round 12
// speedup vs baseline: 2.0815x; 1.0133x over previous
#include <cuda_runtime.h>
#include <cuda_fp16.h>
#include <math.h>
#include <stdint.h>

// ---------------------------------------------------------------------------
// Problem constants
// ---------------------------------------------------------------------------
#define B_     4
#define NTOK   8192
#define MTOK   1024
#define DMODEL 1024
#define H_     16
#define DH     64
#define EPSF   1e-6f
#define NCHUNK 9               // 9216 / 1024

// ---------------------------------------------------------------------------
// Scratch (static device globals; no allocation allowed)
// ---------------------------------------------------------------------------
__device__ __half g_qkv [(size_t)B_ * NTOK * 3 * DMODEL];   // fp16 intermediates
__device__ __half g_ckv [(size_t)B_ * MTOK * 2 * DMODEL];
__device__ float  g_kvp [(size_t)NCHUNK * 64 * DH * DH];
__device__ float  g_ksp [(size_t)NCHUNK * 64 * DH];
__device__ float  g_kv  [64 * DH * DH];
__device__ float  g_ksum[64 * DH];
__device__ __half g_ah  [(size_t)B_ * NTOK * DMODEL];
__device__ __half g_yh  [(size_t)B_ * MTOK * DMODEL];
__device__ __half g_wh  [(size_t)6 * DMODEL * DMODEL];  // qkv(3M)+ckv(2M)+out(1M)

// ---------------------------------------------------------------------------
// PTX helpers (sm_80-compatible: cp.async, ldmatrix, mma.sync)
// ---------------------------------------------------------------------------
__device__ __forceinline__ uint32_t smem_u32(const void* p) {
    uint32_t a;
    asm("{ .reg .u64 t; cvta.to.shared.u64 t, %1; cvt.u32.u64 %0, t; }"
        : "=r"(a) : "l"(p));
    return a;
}
__device__ __forceinline__ void cp16(uint32_t s, const void* g) {
    asm volatile("cp.async.cg.shared.global [%0], [%1], 16;" :: "r"(s), "l"(g));
}
#define CP_COMMIT() asm volatile("cp.async.commit_group;" ::: "memory")
#define CP_WAIT1()  asm volatile("cp.async.wait_group 1;" ::: "memory")
#define CP_WAIT0()  asm volatile("cp.async.wait_group 0;" ::: "memory")

__device__ __forceinline__ void ldsm_x4(uint32_t& r0, uint32_t& r1,
                                        uint32_t& r2, uint32_t& r3, uint32_t addr) {
    asm volatile("ldmatrix.sync.aligned.m8n8.x4.shared.b16 {%0,%1,%2,%3}, [%4];"
                 : "=r"(r0), "=r"(r1), "=r"(r2), "=r"(r3) : "r"(addr));
}
__device__ __forceinline__ void mma_f16(float* c, const uint32_t* a, const uint32_t* b) {
    asm volatile(
        "mma.sync.aligned.m16n8k16.row.col.f32.f16.f16.f32 "
        "{%0,%1,%2,%3}, {%4,%5,%6,%7}, {%8,%9}, {%0,%1,%2,%3};"
        : "+f"(c[0]), "+f"(c[1]), "+f"(c[2]), "+f"(c[3])
        : "r"(a[0]), "r"(a[1]), "r"(a[2]), "r"(a[3]), "r"(b[0]), "r"(b[1]));
}

// ---------------------------------------------------------------------------
// Convert fp32 -> fp16 (elementwise, float4 per thread)
// ---------------------------------------------------------------------------
__global__ void __launch_bounds__(256) conv_h(
    const float* __restrict__ in, __half* __restrict__ hi, int n4)
{
    const int i = blockIdx.x * blockDim.x + threadIdx.x;
    if (i >= n4) return;
    const float4 v = reinterpret_cast<const float4*>(in)[i];
    reinterpret_cast<__half2*>(hi)[2 * i]     = __halves2half2(__float2half(v.x), __float2half(v.y));
    reinterpret_cast<__half2*>(hi)[2 * i + 1] = __halves2half2(__float2half(v.z), __float2half(v.w));
}

// ---------------------------------------------------------------------------
// Transpose weights: w[1024, C] fp32 -> t[C, 1024] fp16
// ---------------------------------------------------------------------------
__global__ void __launch_bounds__(256) conv_w_t(
    const float* __restrict__ w, __half* __restrict__ th, int C)
{
    __shared__ float s[32][33];
    const int c0 = blockIdx.x * 32;
    const int k0 = blockIdx.y * 32;
    const int tx = threadIdx.x;
    const int ty = threadIdx.y;
#pragma unroll
    for (int i = 0; i < 32; i += 8)
        s[ty + i][tx] = w[(size_t)(k0 + ty + i) * C + c0 + tx];
    __syncthreads();
#pragma unroll
    for (int i = 0; i < 32; i += 8)
        th[(size_t)(c0 + ty + i) * DMODEL + k0 + tx] = __float2half(s[tx][ty + i]);
}

// ---------------------------------------------------------------------------
// Shared GEMM mainloop pieces (128x128 tile, BK=32, 8 warps 2x4, 64x32/warp)
// ---------------------------------------------------------------------------
#define BM  128
#define BN  128
#define ROWB 80                       // 64B data + 16B pad
#define OFF_A 0
#define OFF_B 10240
#define STAGE 20480
#define GEMM_SMEM_H 69632             // staging epilogue: 128*132*4 + 1024
#define GEMM_SMEM_F 40960             // 2*STAGE
#define CSTRIDE 132

#define GEMM_MAINLOOP(accvar)                                                   \
    load_tile(0, 0); CP_COMMIT();                                               \
    load_tile(1, 1); CP_COMMIT();                                               \
    for (int kt = 0; kt < 32; kt++) {                                           \
        if (kt < 31) { CP_WAIT1(); } else { CP_WAIT0(); }                       \
        __syncthreads();                                                        \
        const uint32_t base = sb + (kt & 1) * STAGE;                            \
        _Pragma("unroll")                                                       \
        for (int ks = 0; ks < 2; ks++) {                                        \
            uint32_t af[4][4], bf[4][2];                                        \
            _Pragma("unroll")                                                   \
            for (int mt = 0; mt < 4; mt++)                                      \
                ldsm_x4(af[mt][0], af[mt][1], af[mt][2], af[mt][3],             \
                        base + OFF_A + (aRow + mt * 16) * ROWB + ks * 32 + aCol); \
            _Pragma("unroll")                                                   \
            for (int p = 0; p < 2; p++) {                                       \
                uint32_t t0, t1, t2, t3;                                        \
                ldsm_x4(t0, t1, t2, t3,                                         \
                        base + OFF_B + (bRow + p * 16) * ROWB + ks * 32 + bCol);\
                bf[p * 2][0] = t0; bf[p * 2][1] = t1;                           \
                bf[p * 2 + 1][0] = t2; bf[p * 2 + 1][1] = t3;                   \
            }                                                                   \
            _Pragma("unroll")                                                   \
            for (int mt = 0; mt < 4; mt++)                                      \
                _Pragma("unroll")                                               \
                for (int nt = 0; nt < 4; nt++)                                  \
                    mma_f16(accvar[mt][nt], af[mt], bf[nt]);                    \
        }                                                                       \
        __syncthreads();                                                        \
        if (kt + 2 < 32) { load_tile(kt & 1, kt + 2); CP_COMMIT(); }            \
    }

// ---------------------------------------------------------------------------
// GEMM variant H: fp16 output, staged epilogue with fused RMSNorm+ReLU
// ---------------------------------------------------------------------------
__global__ void __launch_bounds__(256, 2) gemm_mma_h(
    const __half* __restrict__ Ah, const __half* __restrict__ Bh,
    const float* __restrict__ bias, __half* __restrict__ C, int Nd,
    int nlimit, const float* __restrict__ wq, const float* __restrict__ wk)
{
    extern __shared__ char smem[];
    const uint32_t sb = smem_u32(smem);
    const int tid  = threadIdx.x;
    const int wid  = tid >> 5;
    const int lane = tid & 31;
    const int m0 = blockIdx.y * BM;
    const int n0 = blockIdx.x * BN;

    const __half* gA = Ah + (size_t)m0 * 1024;
    const __half* gB = Bh + (size_t)n0 * 1024;

    const int lr = tid >> 1;
    const int lc = (tid & 1) * 2;

    auto load_tile = [&](int buf, int kt) {
        const uint32_t s0 = sb + buf * STAGE + lr * ROWB + lc * 16;
        const size_t   go = (size_t)lr * 1024 + kt * 32 + lc * 8;
        cp16(s0 + OFF_A,      gA + go);
        cp16(s0 + OFF_A + 16, gA + go + 8);
        cp16(s0 + OFF_B,      gB + go);
        cp16(s0 + OFF_B + 16, gB + go + 8);
    };

    const int mbase = (wid >> 2) * 64;
    const int nbase = (wid & 3) * 32;
    const int aRow = mbase + (lane & 15);
    const int aCol = (lane >> 4) * 16;
    const int bRow = nbase + ((lane >> 4) << 3) + (lane & 7);
    const int bCol = ((lane >> 3) & 1) * 16;

    float acc[4][4][4];
#pragma unroll
    for (int i = 0; i < 4; i++)
#pragma unroll
        for (int j = 0; j < 4; j++)
#pragma unroll
            for (int k = 0; k < 4; k++) acc[i][j][k] = 0.0f;

    GEMM_MAINLOOP(acc)

    // ---- Epilogue: stage (acc+bias) to smem, fused RMSNorm+ReLU, fp16 store
    __syncthreads();
    float* cs = (float*)smem;
    float* sc = cs + 128 * CSTRIDE;
    {
        const int erow = lane >> 2;
        const int ecol = (lane & 3) * 2;
#pragma unroll
        for (int nt = 0; nt < 4; nt++) {
            const int col = nbase + nt * 8 + ecol;
            const float bx = bias[n0 + col], by = bias[n0 + col + 1];
#pragma unroll
            for (int mt = 0; mt < 4; mt++) {
                const int r0 = mbase + mt * 16 + erow;
                cs[r0 * CSTRIDE + col]           = acc[mt][nt][0] + bx;
                cs[r0 * CSTRIDE + col + 1]       = acc[mt][nt][1] + by;
                cs[(r0 + 8) * CSTRIDE + col]     = acc[mt][nt][2] + bx;
                cs[(r0 + 8) * CSTRIDE + col + 1] = acc[mt][nt][3] + by;
            }
        }
    }
    __syncthreads();

    const bool donorm = (n0 < nlimit);
    if (donorm) {
        const int row  = tid >> 1;
        const int head = tid & 1;
        const float* rp = cs + row * CSTRIDE + head * 64;
        float ss = 0.0f;
#pragma unroll
        for (int j = 0; j < 64; j += 4) {
            float4 v = *(const float4*)(rp + j);
            ss += v.x * v.x + v.y * v.y + v.z * v.z + v.w * v.w;
        }
        sc[tid] = rsqrtf(ss * (1.0f / 64.0f) + EPSF);
        __syncthreads();
    }

    const float* wv = (n0 < 1024) ? wq : wk;
#pragma unroll
    for (int i = 0; i < 16; i++) {
        const int idx = i * 256 + tid;
        const int row = idx >> 5;
        const int c4  = (idx & 31) * 4;
        float4 v = *(float4*)(cs + row * CSTRIDE + c4);
        if (donorm) {
            const float s = sc[row * 2 + (c4 >> 6)];
            const float4 w4 = *(const float4*)(wv + (c4 & 63));
            v.x = fmaxf(v.x * s * w4.x, 0.0f);
            v.y = fmaxf(v.y * s * w4.y, 0.0f);
            v.z = fmaxf(v.z * s * w4.z, 0.0f);
            v.w = fmaxf(v.w * s * w4.w, 0.0f);
        }
        const __half2 h01 = __halves2half2(__float2half(v.x), __float2half(v.y));
        const __half2 h23 = __halves2half2(__float2half(v.z), __float2half(v.w));
        uint2 pk;
        pk.x = *(const uint32_t*)&h01;
        pk.y = *(const uint32_t*)&h23;
        *(uint2*)(C + (size_t)(m0 + row) * Nd + n0 + c4) = pk;
    }
}

// ---------------------------------------------------------------------------
// GEMM variant F: fp32 output, direct-store epilogue (no norm, no staging)
// ---------------------------------------------------------------------------
__global__ void __launch_bounds__(256, 2) gemm_mma_f(
    const __half* __restrict__ Ah, const __half* __restrict__ Bh,
    const float* __restrict__ bias, float* __restrict__ C, int Nd)
{
    extern __shared__ char smem[];
    const uint32_t sb = smem_u32(smem);
    const int tid  = threadIdx.x;
    const int wid  = tid >> 5;
    const int lane = tid & 31;
    const int m0 = blockIdx.y * BM;
    const int n0 = blockIdx.x * BN;

    const __half* gA = Ah + (size_t)m0 * 1024;
    const __half* gB = Bh + (size_t)n0 * 1024;

    const int lr = tid >> 1;
    const int lc = (tid & 1) * 2;

    auto load_tile = [&](int buf, int kt) {
        const uint32_t s0 = sb + buf * STAGE + lr * ROWB + lc * 16;
        const size_t   go = (size_t)lr * 1024 + kt * 32 + lc * 8;
        cp16(s0 + OFF_A,      gA + go);
        cp16(s0 + OFF_A + 16, gA + go + 8);
        cp16(s0 + OFF_B,      gB + go);
        cp16(s0 + OFF_B + 16, gB + go + 8);
    };

    const int mbase = (wid >> 2) * 64;
    const int nbase = (wid & 3) * 32;
    const int aRow = mbase + (lane & 15);
    const int aCol = (lane >> 4) * 16;
    const int bRow = nbase + ((lane >> 4) << 3) + (lane & 7);
    const int bCol = ((lane >> 3) & 1) * 16;

    float acc[4][4][4];
#pragma unroll
    for (int i = 0; i < 4; i++)
#pragma unroll
        for (int j = 0; j < 4; j++)
#pragma unroll
            for (int k = 0; k < 4; k++) acc[i][j][k] = 0.0f;

    GEMM_MAINLOOP(acc)

    // direct stores (32B-sector coalesced per 4-lane group)
    const int erow = lane >> 2;
    const int ecol = (lane & 3) * 2;
#pragma unroll
    for (int mt = 0; mt < 4; mt++)
#pragma unroll
        for (int nt = 0; nt < 4; nt++) {
            const int col = n0 + nbase + nt * 8 + ecol;
            const float bx = bias[col], by = bias[col + 1];
            const int row0 = m0 + mbase + mt * 16 + erow;
            float2 v0 = make_float2(acc[mt][nt][0] + bx, acc[mt][nt][1] + by);
            float2 v1 = make_float2(acc[mt][nt][2] + bx, acc[mt][nt][3] + by);
            *(float2*)(C + (size_t)row0 * Nd + col)       = v0;
            *(float2*)(C + (size_t)(row0 + 8) * Nd + col) = v1;
        }
}

// ---------------------------------------------------------------------------
// kv[b,h,d,e] = sum_s k[s,d] v[s,e];  ksum[b,h,d] = sum_s k[s,d]
// fp16 inputs, fp32 accumulation, chunked partials (deterministic)
// ---------------------------------------------------------------------------
#define SCHUNK 1024
#define SSUB   16

__global__ void kv_accum(const __half* __restrict__ qkv, const __half* __restrict__ ckv,
                         float* __restrict__ kvp, float* __restrict__ ksp)
{
    const int bh = blockIdx.y;
    const int b  = bh >> 4;
    const int h  = bh & 15;
    const int s0 = blockIdx.x * SCHUNK;

    __shared__ float sk[SSUB][DH];
    __shared__ float sv[SSUB][DH];

    const int tid = threadIdx.x;
    const int d   = tid >> 2;
    const int eg  = tid & 3;
    // vector-load mapping: 256 chunks of 4 halves cover SSUB*DH = 1024 elems
    const int lsi = tid >> 4;          // 0..15
    const int ldd = (tid & 15) * 4;    // 0..60

    float acc[16];
#pragma unroll
    for (int j = 0; j < 16; j++) acc[j] = 0.0f;
    float ksl = 0.0f;

    for (int st = s0; st < s0 + SCHUNK; st += SSUB) {
        {
            const int s = st + lsi;
            const __half *rk, *rv;
            if (s < NTOK) {
                const __half* row = qkv + (size_t)(b * NTOK + s) * (3 * DMODEL);
                rk = row + DMODEL + h * DH + ldd;
                rv = row + 2 * DMODEL + h * DH + ldd;
            } else {
                const __half* row = ckv + (size_t)(b * MTOK + (s - NTOK)) * (2 * DMODEL);
                rk = row + h * DH + ldd;
                rv = row + DMODEL + h * DH + ldd;
            }
            const __half2 k01 = *(const __half2*)(rk);
            const __half2 k23 = *(const __half2*)(rk + 2);
            const __half2 v01 = *(const __half2*)(rv);
            const __half2 v23 = *(const __half2*)(rv + 2);
            const float2 fk01 = __half22float2(k01), fk23 = __half22float2(k23);
            const float2 fv01 = __half22float2(v01), fv23 = __half22float2(v23);
            sk[lsi][ldd]     = fk01.x; sk[lsi][ldd + 1] = fk01.y;
            sk[lsi][ldd + 2] = fk23.x; sk[lsi][ldd + 3] = fk23.y;
            sv[lsi][ldd]     = fv01.x; sv[lsi][ldd + 1] = fv01.y;
            sv[lsi][ldd + 2] = fv23.x; sv[lsi][ldd + 3] = fv23.y;
        }
        __syncthreads();
#pragma unroll
        for (int si = 0; si < SSUB; si++) {
            const float kd = sk[si][d];
            if (eg == 0) ksl += kd;
#pragma unroll
            for (int j = 0; j < 16; j++)
                acc[j] = fmaf(kd, sv[si][eg * 16 + j], acc[j]);
        }
        __syncthreads();
    }

    float* kvpp = kvp + (size_t)blockIdx.x * 64 * DH * DH + (size_t)bh * DH * DH + d * DH + eg * 16;
#pragma unroll
    for (int j = 0; j < 16; j++) kvpp[j] = acc[j];
    if (eg == 0) ksp[(size_t)blockIdx.x * 64 * DH + bh * DH + d] = ksl;
}

__global__ void kv_reduce(const float* __restrict__ kvp, const float* __restrict__ ksp,
                          float* __restrict__ kv, float* __restrict__ ksum)
{
    const int idx = blockIdx.x * blockDim.x + threadIdx.x;
    if (idx < 64 * DH * DH) {
        float s = 0.0f;
#pragma unroll
        for (int c = 0; c < NCHUNK; c++) s += kvp[(size_t)c * 64 * DH * DH + idx];
        kv[idx] = s;
    }
    if (idx < 64 * DH) {
        float s = 0.0f;
#pragma unroll
        for (int c = 0; c < NCHUNK; c++) s += ksp[(size_t)c * 64 * DH + idx];
        ksum[idx] = s;
    }
}

// ---------------------------------------------------------------------------
// attn = (q @ kv) / (q . ksum + eps); fp16 q in, fp16 out
// ---------------------------------------------------------------------------
__global__ void attn_apply(const __half* __restrict__ qkv, const float* __restrict__ kv,
                           const float* __restrict__ ksum, __half* __restrict__ oh)
{
    const int bh = blockIdx.y;
    const int b  = bh >> 4;
    const int h  = bh & 15;

    __shared__ float skv[DH * DH];
    __shared__ float sks[DH];

    const int tid = threadIdx.x;
    for (int i = tid; i < DH * DH; i += 256) skv[i] = kv[(size_t)bh * DH * DH + i];
    if (tid < DH) sks[tid] = ksum[bh * DH + tid];
    __syncthreads();

    const int warp = tid >> 5;
    const int lane = tid & 31;
    const int t0   = blockIdx.x * 64 + warp * 8;

    for (int i = 0; i < 8; i++) {
        const int t = t0 + i;
        const __half* qp = qkv + (size_t)(b * NTOK + t) * (3 * DMODEL) + h * DH;
        const float q0 = __half2float(qp[lane]);
        const float q1 = __half2float(qp[lane + 32]);

        float sc = q0 * sks[lane] + q1 * sks[lane + 32];
#pragma unroll
        for (int o = 16; o > 0; o >>= 1) sc += __shfl_xor_sync(0xffffffffu, sc, o);
        const float inv = 1.0f / (sc + EPSF);

        float a0 = 0.0f, a1 = 0.0f;
#pragma unroll
        for (int d = 0; d < 32; d++) {
            const float qd = __shfl_sync(0xffffffffu, q0, d);
            a0 = fmaf(qd, skv[d * DH + lane], a0);
            a1 = fmaf(qd, skv[d * DH + lane + 32], a1);
        }
#pragma unroll
        for (int d = 0; d < 32; d++) {
            const float qd = __shfl_sync(0xffffffffu, q1, d);
            a0 = fmaf(qd, skv[(d + 32) * DH + lane], a0);
            a1 = fmaf(qd, skv[(d + 32) * DH + lane + 32], a1);
        }

        const size_t o0 = (size_t)(b * NTOK + t) * DMODEL + h * DH;
        oh[o0 + lane]      = __float2half(a0 * inv);
        oh[o0 + lane + 32] = __float2half(a1 * inv);
    }
}

// ---------------------------------------------------------------------------
// Launch — QKV GEMM placed at my idx 3 (= absolute idx 5 with 2 harness
// pre-launches) so ncu captures the GEMM roofline.
// ---------------------------------------------------------------------------
extern "C" void kernel_launch(void* const* d_in, const int* in_sizes, int n_in,
                              void* d_out, int out_size)
{
    const float* x     = (const float*)d_in[0];
    const float* y     = (const float*)d_in[1];
    const float* w_qkv = (const float*)d_in[2];
    const float* b_qkv = (const float*)d_in[3];
    const float* w_ckv = (const float*)d_in[4];
    const float* b_ckv = (const float*)d_in[5];
    const float* w_out = (const float*)d_in[6];
    const float* b_out = (const float*)d_in[7];
    const float* qn_w  = (const float*)d_in[8];
    const float* kn_w  = (const float*)d_in[9];
    const float* ckn_w = (const float*)d_in[10];
    float* out = (float*)d_out;

    float *p_kvp, *p_ksp, *p_kv, *p_ksum;
    __half *p_qkv, *p_ckv, *p_ah, *p_yh, *p_wh;
    cudaGetSymbolAddress((void**)&p_qkv,  g_qkv);
    cudaGetSymbolAddress((void**)&p_ckv,  g_ckv);
    cudaGetSymbolAddress((void**)&p_kvp,  g_kvp);
    cudaGetSymbolAddress((void**)&p_ksp,  g_ksp);
    cudaGetSymbolAddress((void**)&p_kv,   g_kv);
    cudaGetSymbolAddress((void**)&p_ksum, g_ksum);
    cudaGetSymbolAddress((void**)&p_ah,   g_ah);
    cudaGetSymbolAddress((void**)&p_yh,   g_yh);
    cudaGetSymbolAddress((void**)&p_wh,   g_wh);

    // weight regions: [0,3M) qkv, [3M,5M) ckv, [5M,6M) out
    const size_t W_QKV = 0;
    const size_t W_CKV = (size_t)3 * DMODEL * DMODEL;
    const size_t W_OUT = (size_t)5 * DMODEL * DMODEL;

    cudaFuncSetAttribute(gemm_mma_h, cudaFuncAttributeMaxDynamicSharedMemorySize, GEMM_SMEM_H);
    cudaFuncSetAttribute(gemm_mma_f, cudaFuncAttributeMaxDynamicSharedMemorySize, GEMM_SMEM_F);

    const dim3 blk(256);
    const dim3 wblk(32, 8);
    const int MR = B_ * NTOK;   // 32768
    const int YR = B_ * MTOK;   // 4096

    // [0] qkv weight transpose, [1] x conv, [2] y conv
    conv_w_t<<<dim3(3 * DMODEL / 32, DMODEL / 32), wblk>>>(w_qkv, p_wh + W_QKV, 3 * DMODEL);
    conv_h<<<(MR * DMODEL / 4 + 255) / 256, blk>>>(x, p_ah, MR * DMODEL / 4);
    conv_h<<<(YR * DMODEL / 4 + 255) / 256, blk>>>(y, p_yh, YR * DMODEL / 4);

    // [3] QKV GEMM (ncu capture target) with fused q/k RMSNorm+ReLU
    gemm_mma_h<<<dim3(3 * DMODEL / BN, MR / BM), blk, GEMM_SMEM_H>>>(
        p_ah, p_wh + W_QKV, b_qkv, p_qkv, 3 * DMODEL, 2048, qn_w, kn_w);

    // [4] ckv weight transpose, [5] CKV GEMM with fused c_k RMSNorm+ReLU
    conv_w_t<<<dim3(2 * DMODEL / 32, DMODEL / 32), wblk>>>(w_ckv, p_wh + W_CKV, 2 * DMODEL);
    gemm_mma_h<<<dim3(2 * DMODEL / BN, YR / BM), blk, GEMM_SMEM_H>>>(
        p_yh, p_wh + W_CKV, b_ckv, p_ckv, 2 * DMODEL, 1024, ckn_w, ckn_w);

    // [6] out weight transpose
    conv_w_t<<<dim3(DMODEL / 32, DMODEL / 32), wblk>>>(w_out, p_wh + W_OUT, DMODEL);

    // [7..8] kv + k_sum
    kv_accum<<<dim3(NCHUNK, 64), blk>>>(p_qkv, p_ckv, p_kvp, p_ksp);
    kv_reduce<<<(64 * DH * DH + 255) / 256, blk>>>(p_kvp, p_ksp, p_kv, p_ksum);

    // [9] attn (writes fp16 directly into x-side buffer)
    attn_apply<<<dim3(NTOK / 64, 64), blk>>>(p_qkv, p_kv, p_ksum, p_ah);

    // [10] output GEMM (fp32 direct-store epilogue)
    gemm_mma_f<<<dim3(DMODEL / BN, MR / BM), blk, GEMM_SMEM_F>>>(
        p_ah, p_wh + W_OUT, b_out, out, DMODEL);
}

// round 14
// speedup vs baseline: 2.2471x; 1.0796x over previous
#include <cuda_runtime.h>
#include <cuda_fp16.h>
#include <math.h>
#include <stdint.h>

// ---------------------------------------------------------------------------
// Problem constants
// ---------------------------------------------------------------------------
#define B_     4
#define NTOK   8192
#define MTOK   1024
#define DMODEL 1024
#define H_     16
#define DH     64
#define EPSF   1e-6f
#define NCHUNK 9               // 9216 / 1024

// ---------------------------------------------------------------------------
// Scratch (static device globals; no allocation allowed)
// ---------------------------------------------------------------------------
__device__ __half g_qkv [(size_t)B_ * NTOK * 3 * DMODEL];   // fp16 intermediates
__device__ __half g_ckv [(size_t)B_ * MTOK * 2 * DMODEL];
__device__ float  g_kvp [(size_t)NCHUNK * 64 * DH * DH];
__device__ float  g_ksp [(size_t)NCHUNK * 64 * DH];
__device__ float  g_kv  [64 * DH * DH];
__device__ float  g_ksum[64 * DH];
__device__ __half g_ah  [(size_t)B_ * NTOK * DMODEL];
__device__ __half g_yh  [(size_t)B_ * MTOK * DMODEL];
__device__ __half g_wh  [(size_t)6 * DMODEL * DMODEL];  // qkv(3M)+ckv(2M)+out(1M)

// ---------------------------------------------------------------------------
// PTX helpers (sm_80-compatible: cp.async, ldmatrix, mma.sync)
// ---------------------------------------------------------------------------
__device__ __forceinline__ uint32_t smem_u32(const void* p) {
    uint32_t a;
    asm("{ .reg .u64 t; cvta.to.shared.u64 t, %1; cvt.u32.u64 %0, t; }"
        : "=r"(a) : "l"(p));
    return a;
}
__device__ __forceinline__ void cp16(uint32_t s, const void* g) {
    asm volatile("cp.async.cg.shared.global [%0], [%1], 16;" :: "r"(s), "l"(g));
}
#define CP_COMMIT() asm volatile("cp.async.commit_group;" ::: "memory")
#define CP_WAIT2()  asm volatile("cp.async.wait_group 2;" ::: "memory")

__device__ __forceinline__ void ldsm_x4(uint32_t& r0, uint32_t& r1,
                                        uint32_t& r2, uint32_t& r3, uint32_t addr) {
    asm volatile("ldmatrix.sync.aligned.m8n8.x4.shared.b16 {%0,%1,%2,%3}, [%4];"
                 : "=r"(r0), "=r"(r1), "=r"(r2), "=r"(r3) : "r"(addr));
}
__device__ __forceinline__ void mma_f16(float* c, const uint32_t* a, const uint32_t* b) {
    asm volatile(
        "mma.sync.aligned.m16n8k16.row.col.f32.f16.f16.f32 "
        "{%0,%1,%2,%3}, {%4,%5,%6,%7}, {%8,%9}, {%0,%1,%2,%3};"
        : "+f"(c[0]), "+f"(c[1]), "+f"(c[2]), "+f"(c[3])
        : "r"(a[0]), "r"(a[1]), "r"(a[2]), "r"(a[3]), "r"(b[0]), "r"(b[1]));
}

// ---------------------------------------------------------------------------
// Convert fp32 -> fp16 (elementwise, float4 per thread)
// ---------------------------------------------------------------------------
__global__ void __launch_bounds__(256) conv_h(
    const float* __restrict__ in, __half* __restrict__ hi, int n4)
{
    const int i = blockIdx.x * blockDim.x + threadIdx.x;
    if (i >= n4) return;
    const float4 v = reinterpret_cast<const float4*>(in)[i];
    reinterpret_cast<__half2*>(hi)[2 * i]     = __halves2half2(__float2half(v.x), __float2half(v.y));
    reinterpret_cast<__half2*>(hi)[2 * i + 1] = __halves2half2(__float2half(v.z), __float2half(v.w));
}

// ---------------------------------------------------------------------------
// Transpose weights: w[1024, C] fp32 -> t[C, 1024] fp16
// ---------------------------------------------------------------------------
__global__ void __launch_bounds__(256) conv_w_t(
    const float* __restrict__ w, __half* __restrict__ th, int C)
{
    __shared__ float s[32][33];
    const int c0 = blockIdx.x * 32;
    const int k0 = blockIdx.y * 32;
    const int tx = threadIdx.x;
    const int ty = threadIdx.y;
#pragma unroll
    for (int i = 0; i < 32; i += 8)
        s[ty + i][tx] = w[(size_t)(k0 + ty + i) * C + c0 + tx];
    __syncthreads();
#pragma unroll
    for (int i = 0; i < 32; i += 8)
        th[(size_t)(c0 + ty + i) * DMODEL + k0 + tx] = __float2half(s[tx][ty + i]);
}

// ---------------------------------------------------------------------------
// Shared GEMM mainloop (128x128 tile, BK=32, 8 warps 2x4, 64x32/warp)
// 4-stage cp.async pipeline, ONE __syncthreads per iteration.
// ---------------------------------------------------------------------------
#define BM  128
#define BN  128
#define ROWB 80                       // 64B data + 16B pad
#define OFF_A 0
#define OFF_B 10240
#define STAGE 20480
#define NST   4
#define GEMM_SMEM (NST * STAGE)       // 81920 (also covers epi 68608)
#define CSTRIDE 132

// Pipeline invariants: stages kt..kt+2 in flight at loop head (3 groups);
// wait_group 2 completes stage kt. Load at iter kt targets buffer (kt+3)&3
// = (kt-1)&3, whose compute finished before this iteration's barrier.
// Empty commit groups keep the outstanding-count arithmetic exact.
#define GEMM_MAINLOOP(accvar)                                                   \
    load_tile(0, 0); CP_COMMIT();                                               \
    load_tile(1, 1); CP_COMMIT();                                               \
    load_tile(2, 2); CP_COMMIT();                                               \
    for (int kt = 0; kt < 32; kt++) {                                           \
        CP_WAIT2();                                                             \
        __syncthreads();                                                        \
        if (kt + 3 < 32) load_tile((kt + 3) & 3, kt + 3);                       \
        CP_COMMIT();                                                            \
        const uint32_t base = sb + (kt & 3) * STAGE;                            \
        _Pragma("unroll")                                                       \
        for (int ks = 0; ks < 2; ks++) {                                        \
            uint32_t af[4][4], bf[4][2];                                        \
            _Pragma("unroll")                                                   \
            for (int mt = 0; mt < 4; mt++)                                      \
                ldsm_x4(af[mt][0], af[mt][1], af[mt][2], af[mt][3],             \
                        base + OFF_A + (aRow + mt * 16) * ROWB + ks * 32 + aCol); \
            _Pragma("unroll")                                                   \
            for (int p = 0; p < 2; p++) {                                       \
                uint32_t t0, t1, t2, t3;                                        \
                ldsm_x4(t0, t1, t2, t3,                                         \
                        base + OFF_B + (bRow + p * 16) * ROWB + ks * 32 + bCol);\
                bf[p * 2][0] = t0; bf[p * 2][1] = t1;                           \
                bf[p * 2 + 1][0] = t2; bf[p * 2 + 1][1] = t3;                   \
            }                                                                   \
            _Pragma("unroll")                                                   \
            for (int mt = 0; mt < 4; mt++)                                      \
                _Pragma("unroll")                                               \
                for (int nt = 0; nt < 4; nt++)                                  \
                    mma_f16(accvar[mt][nt], af[mt], bf[nt]);                    \
        }                                                                       \
    }

// ---------------------------------------------------------------------------
// GEMM variant H: fp16 output, staged epilogue with fused RMSNorm+ReLU
// ---------------------------------------------------------------------------
__global__ void __launch_bounds__(256, 2) gemm_mma_h(
    const __half* __restrict__ Ah, const __half* __restrict__ Bh,
    const float* __restrict__ bias, __half* __restrict__ C, int Nd,
    int nlimit, const float* __restrict__ wq, const float* __restrict__ wk)
{
    extern __shared__ char smem[];
    const uint32_t sb = smem_u32(smem);
    const int tid  = threadIdx.x;
    const int wid  = tid >> 5;
    const int lane = tid & 31;
    const int m0 = blockIdx.y * BM;
    const int n0 = blockIdx.x * BN;

    const __half* gA = Ah + (size_t)m0 * 1024;
    const __half* gB = Bh + (size_t)n0 * 1024;

    const int lr = tid >> 1;
    const int lc = (tid & 1) * 2;

    auto load_tile = [&](int buf, int kt) {
        const uint32_t s0 = sb + buf * STAGE + lr * ROWB + lc * 16;
        const size_t   go = (size_t)lr * 1024 + kt * 32 + lc * 8;
        cp16(s0 + OFF_A,      gA + go);
        cp16(s0 + OFF_A + 16, gA + go + 8);
        cp16(s0 + OFF_B,      gB + go);
        cp16(s0 + OFF_B + 16, gB + go + 8);
    };

    const int mbase = (wid >> 2) * 64;
    const int nbase = (wid & 3) * 32;
    const int aRow = mbase + (lane & 15);
    const int aCol = (lane >> 4) * 16;
    const int bRow = nbase + ((lane >> 4) << 3) + (lane & 7);
    const int bCol = ((lane >> 3) & 1) * 16;

    float acc[4][4][4];
#pragma unroll
    for (int i = 0; i < 4; i++)
#pragma unroll
        for (int j = 0; j < 4; j++)
#pragma unroll
            for (int k = 0; k < 4; k++) acc[i][j][k] = 0.0f;

    GEMM_MAINLOOP(acc)

    // ---- Epilogue: stage (acc+bias) to smem, fused RMSNorm+ReLU, fp16 store
    __syncthreads();
    float* cs = (float*)smem;
    float* sc = cs + 128 * CSTRIDE;
    {
        const int erow = lane >> 2;
        const int ecol = (lane & 3) * 2;
#pragma unroll
        for (int nt = 0; nt < 4; nt++) {
            const int col = nbase + nt * 8 + ecol;
            const float bx = bias[n0 + col], by = bias[n0 + col + 1];
#pragma unroll
            for (int mt = 0; mt < 4; mt++) {
                const int r0 = mbase + mt * 16 + erow;
                cs[r0 * CSTRIDE + col]           = acc[mt][nt][0] + bx;
                cs[r0 * CSTRIDE + col + 1]       = acc[mt][nt][1] + by;
                cs[(r0 + 8) * CSTRIDE + col]     = acc[mt][nt][2] + bx;
                cs[(r0 + 8) * CSTRIDE + col + 1] = acc[mt][nt][3] + by;
            }
        }
    }
    __syncthreads();

    const bool donorm = (n0 < nlimit);
    if (donorm) {
        const int row  = tid >> 1;
        const int head = tid & 1;
        const float* rp = cs + row * CSTRIDE + head * 64;
        float ss = 0.0f;
#pragma unroll
        for (int j = 0; j < 64; j += 4) {
            float4 v = *(const float4*)(rp + j);
            ss += v.x * v.x + v.y * v.y + v.z * v.z + v.w * v.w;
        }
        sc[tid] = rsqrtf(ss * (1.0f / 64.0f) + EPSF);
        __syncthreads();
    }

    const float* wv = (n0 < 1024) ? wq : wk;
#pragma unroll
    for (int i = 0; i < 16; i++) {
        const int idx = i * 256 + tid;
        const int row = idx >> 5;
        const int c4  = (idx & 31) * 4;
        float4 v = *(float4*)(cs + row * CSTRIDE + c4);
        if (donorm) {
            const float s = sc[row * 2 + (c4 >> 6)];
            const float4 w4 = *(const float4*)(wv + (c4 & 63));
            v.x = fmaxf(v.x * s * w4.x, 0.0f);
            v.y = fmaxf(v.y * s * w4.y, 0.0f);
            v.z = fmaxf(v.z * s * w4.z, 0.0f);
            v.w = fmaxf(v.w * s * w4.w, 0.0f);
        }
        const __half2 h01 = __halves2half2(__float2half(v.x), __float2half(v.y));
        const __half2 h23 = __halves2half2(__float2half(v.z), __float2half(v.w));
        uint2 pk;
        pk.x = *(const uint32_t*)&h01;
        pk.y = *(const uint32_t*)&h23;
        *(uint2*)(C + (size_t)(m0 + row) * Nd + n0 + c4) = pk;
    }
}

// ---------------------------------------------------------------------------
// GEMM variant F: fp32 output, direct-store epilogue (no norm, no staging)
// ---------------------------------------------------------------------------
__global__ void __launch_bounds__(256, 2) gemm_mma_f(
    const __half* __restrict__ Ah, const __half* __restrict__ Bh,
    const float* __restrict__ bias, float* __restrict__ C, int Nd)
{
    extern __shared__ char smem[];
    const uint32_t sb = smem_u32(smem);
    const int tid  = threadIdx.x;
    const int wid  = tid >> 5;
    const int lane = tid & 31;
    const int m0 = blockIdx.y * BM;
    const int n0 = blockIdx.x * BN;

    const __half* gA = Ah + (size_t)m0 * 1024;
    const __half* gB = Bh + (size_t)n0 * 1024;

    const int lr = tid >> 1;
    const int lc = (tid & 1) * 2;

    auto load_tile = [&](int buf, int kt) {
        const uint32_t s0 = sb + buf * STAGE + lr * ROWB + lc * 16;
        const size_t   go = (size_t)lr * 1024 + kt * 32 + lc * 8;
        cp16(s0 + OFF_A,      gA + go);
        cp16(s0 + OFF_A + 16, gA + go + 8);
        cp16(s0 + OFF_B,      gB + go);
        cp16(s0 + OFF_B + 16, gB + go + 8);
    };

    const int mbase = (wid >> 2) * 64;
    const int nbase = (wid & 3) * 32;
    const int aRow = mbase + (lane & 15);
    const int aCol = (lane >> 4) * 16;
    const int bRow = nbase + ((lane >> 4) << 3) + (lane & 7);
    const int bCol = ((lane >> 3) & 1) * 16;

    float acc[4][4][4];
#pragma unroll
    for (int i = 0; i < 4; i++)
#pragma unroll
        for (int j = 0; j < 4; j++)
#pragma unroll
            for (int k = 0; k < 4; k++) acc[i][j][k] = 0.0f;

    GEMM_MAINLOOP(acc)

    // direct stores (32B-sector coalesced per 4-lane group)
    const int erow = lane >> 2;
    const int ecol = (lane & 3) * 2;
#pragma unroll
    for (int mt = 0; mt < 4; mt++)
#pragma unroll
        for (int nt = 0; nt < 4; nt++) {
            const int col = n0 + nbase + nt * 8 + ecol;
            const float bx = bias[col], by = bias[col + 1];
            const int row0 = m0 + mbase + mt * 16 + erow;
            float2 v0 = make_float2(acc[mt][nt][0] + bx, acc[mt][nt][1] + by);
            float2 v1 = make_float2(acc[mt][nt][2] + bx, acc[mt][nt][3] + by);
            *(float2*)(C + (size_t)row0 * Nd + col)       = v0;
            *(float2*)(C + (size_t)(row0 + 8) * Nd + col) = v1;
        }
}

// ---------------------------------------------------------------------------
// kv[b,h,d,e] = sum_s k[s,d] v[s,e];  ksum[b,h,d] = sum_s k[s,d]
// fp16 inputs, fp32 accumulation, chunked partials (deterministic)
// ---------------------------------------------------------------------------
#define SCHUNK 1024
#define SSUB   16

__global__ void kv_accum(const __half* __restrict__ qkv, const __half* __restrict__ ckv,
                         float* __restrict__ kvp, float* __restrict__ ksp)
{
    const int bh = blockIdx.y;
    const int b  = bh >> 4;
    const int h  = bh & 15;
    const int s0 = blockIdx.x * SCHUNK;

    __shared__ float sk[SSUB][DH];
    __shared__ float sv[SSUB][DH];

    const int tid = threadIdx.x;
    const int d   = tid >> 2;
    const int eg  = tid & 3;
    const int lsi = tid >> 4;          // 0..15
    const int ldd = (tid & 15) * 4;    // 0..60

    float acc[16];
#pragma unroll
    for (int j = 0; j < 16; j++) acc[j] = 0.0f;
    float ksl = 0.0f;

    for (int st = s0; st < s0 + SCHUNK; st += SSUB) {
        {
            const int s = st + lsi;
            const __half *rk, *rv;
            if (s < NTOK) {
                const __half* row = qkv + (size_t)(b * NTOK + s) * (3 * DMODEL);
                rk = row + DMODEL + h * DH + ldd;
                rv = row + 2 * DMODEL + h * DH + ldd;
            } else {
                const __half* row = ckv + (size_t)(b * MTOK + (s - NTOK)) * (2 * DMODEL);
                rk = row + h * DH + ldd;
                rv = row + DMODEL + h * DH + ldd;
            }
            const __half2 k01 = *(const __half2*)(rk);
            const __half2 k23 = *(const __half2*)(rk + 2);
            const __half2 v01 = *(const __half2*)(rv);
            const __half2 v23 = *(const __half2*)(rv + 2);
            const float2 fk01 = __half22float2(k01), fk23 = __half22float2(k23);
            const float2 fv01 = __half22float2(v01), fv23 = __half22float2(v23);
            sk[lsi][ldd]     = fk01.x; sk[lsi][ldd + 1] = fk01.y;
            sk[lsi][ldd + 2] = fk23.x; sk[lsi][ldd + 3] = fk23.y;
            sv[lsi][ldd]     = fv01.x; sv[lsi][ldd + 1] = fv01.y;
            sv[lsi][ldd + 2] = fv23.x; sv[lsi][ldd + 3] = fv23.y;
        }
        __syncthreads();
#pragma unroll
        for (int si = 0; si < SSUB; si++) {
            const float kd = sk[si][d];
            if (eg == 0) ksl += kd;
#pragma unroll
            for (int j = 0; j < 16; j++)
                acc[j] = fmaf(kd, sv[si][eg * 16 + j], acc[j]);
        }
        __syncthreads();
    }

    float* kvpp = kvp + (size_t)blockIdx.x * 64 * DH * DH + (size_t)bh * DH * DH + d * DH + eg * 16;
#pragma unroll
    for (int j = 0; j < 16; j++) kvpp[j] = acc[j];
    if (eg == 0) ksp[(size_t)blockIdx.x * 64 * DH + bh * DH + d] = ksl;
}

__global__ void kv_reduce(const float* __restrict__ kvp, const float* __restrict__ ksp,
                          float* __restrict__ kv, float* __restrict__ ksum)
{
    const int idx = blockIdx.x * blockDim.x + threadIdx.x;
    if (idx < 64 * DH * DH) {
        float s = 0.0f;
#pragma unroll
        for (int c = 0; c < NCHUNK; c++) s += kvp[(size_t)c * 64 * DH * DH + idx];
        kv[idx] = s;
    }
    if (idx < 64 * DH) {
        float s = 0.0f;
#pragma unroll
        for (int c = 0; c < NCHUNK; c++) s += ksp[(size_t)c * 64 * DH + idx];
        ksum[idx] = s;
    }
}

// ---------------------------------------------------------------------------
// attn = (q @ kv) / (q . ksum + eps); fp16 q in, fp16 out
// ---------------------------------------------------------------------------
__global__ void attn_apply(const __half* __restrict__ qkv, const float* __restrict__ kv,
                           const float* __restrict__ ksum, __half* __restrict__ oh)
{
    const int bh = blockIdx.y;
    const int b  = bh >> 4;
    const int h  = bh & 15;

    __shared__ float skv[DH * DH];
    __shared__ float sks[DH];

    const int tid = threadIdx.x;
    for (int i = tid; i < DH * DH; i += 256) skv[i] = kv[(size_t)bh * DH * DH + i];
    if (tid < DH) sks[tid] = ksum[bh * DH + tid];
    __syncthreads();

    const int warp = tid >> 5;
    const int lane = tid & 31;
    const int t0   = blockIdx.x * 64 + warp * 8;

    for (int i = 0; i < 8; i++) {
        const int t = t0 + i;
        const __half* qp = qkv + (size_t)(b * NTOK + t) * (3 * DMODEL) + h * DH;
        const float q0 = __half2float(qp[lane]);
        const float q1 = __half2float(qp[lane + 32]);

        float sc = q0 * sks[lane] + q1 * sks[lane + 32];
#pragma unroll
        for (int o = 16; o > 0; o >>= 1) sc += __shfl_xor_sync(0xffffffffu, sc, o);
        const float inv = 1.0f / (sc + EPSF);

        float a0 = 0.0f, a1 = 0.0f;
#pragma unroll
        for (int d = 0; d < 32; d++) {
            const float qd = __shfl_sync(0xffffffffu, q0, d);
            a0 = fmaf(qd, skv[d * DH + lane], a0);
            a1 = fmaf(qd, skv[d * DH + lane + 32], a1);
        }
#pragma unroll
        for (int d = 0; d < 32; d++) {
            const float qd = __shfl_sync(0xffffffffu, q1, d);
            a0 = fmaf(qd, skv[(d + 32) * DH + lane], a0);
            a1 = fmaf(qd, skv[(d + 32) * DH + lane + 32], a1);
        }

        const size_t o0 = (size_t)(b * NTOK + t) * DMODEL + h * DH;
        oh[o0 + lane]      = __float2half(a0 * inv);
        oh[o0 + lane + 32] = __float2half(a1 * inv);
    }
}

// ---------------------------------------------------------------------------
// Launch — QKV GEMM at my idx 3 (ncu capture slot)
// ---------------------------------------------------------------------------
extern "C" void kernel_launch(void* const* d_in, const int* in_sizes, int n_in,
                              void* d_out, int out_size)
{
    const float* x     = (const float*)d_in[0];
    const float* y     = (const float*)d_in[1];
    const float* w_qkv = (const float*)d_in[2];
    const float* b_qkv = (const float*)d_in[3];
    const float* w_ckv = (const float*)d_in[4];
    const float* b_ckv = (const float*)d_in[5];
    const float* w_out = (const float*)d_in[6];
    const float* b_out = (const float*)d_in[7];
    const float* qn_w  = (const float*)d_in[8];
    const float* kn_w  = (const float*)d_in[9];
    const float* ckn_w = (const float*)d_in[10];
    float* out = (float*)d_out;

    float *p_kvp, *p_ksp, *p_kv, *p_ksum;
    __half *p_qkv, *p_ckv, *p_ah, *p_yh, *p_wh;
    cudaGetSymbolAddress((void**)&p_qkv,  g_qkv);
    cudaGetSymbolAddress((void**)&p_ckv,  g_ckv);
    cudaGetSymbolAddress((void**)&p_kvp,  g_kvp);
    cudaGetSymbolAddress((void**)&p_ksp,  g_ksp);
    cudaGetSymbolAddress((void**)&p_kv,   g_kv);
    cudaGetSymbolAddress((void**)&p_ksum, g_ksum);
    cudaGetSymbolAddress((void**)&p_ah,   g_ah);
    cudaGetSymbolAddress((void**)&p_yh,   g_yh);
    cudaGetSymbolAddress((void**)&p_wh,   g_wh);

    // weight regions: [0,3M) qkv, [3M,5M) ckv, [5M,6M) out
    const size_t W_QKV = 0;
    const size_t W_CKV = (size_t)3 * DMODEL * DMODEL;
    const size_t W_OUT = (size_t)5 * DMODEL * DMODEL;

    cudaFuncSetAttribute(gemm_mma_h, cudaFuncAttributeMaxDynamicSharedMemorySize, GEMM_SMEM);
    cudaFuncSetAttribute(gemm_mma_f, cudaFuncAttributeMaxDynamicSharedMemorySize, GEMM_SMEM);

    const dim3 blk(256);
    const dim3 wblk(32, 8);
    const int MR = B_ * NTOK;   // 32768
    const int YR = B_ * MTOK;   // 4096

    // [0] qkv weight transpose, [1] x conv, [2] y conv
    conv_w_t<<<dim3(3 * DMODEL / 32, DMODEL / 32), wblk>>>(w_qkv, p_wh + W_QKV, 3 * DMODEL);
    conv_h<<<(MR * DMODEL / 4 + 255) / 256, blk>>>(x, p_ah, MR * DMODEL / 4);
    conv_h<<<(YR * DMODEL / 4 + 255) / 256, blk>>>(y, p_yh, YR * DMODEL / 4);

    // [3] QKV GEMM (ncu capture target) with fused q/k RMSNorm+ReLU
    gemm_mma_h<<<dim3(3 * DMODEL / BN, MR / BM), blk, GEMM_SMEM>>>(
        p_ah, p_wh + W_QKV, b_qkv, p_qkv, 3 * DMODEL, 2048, qn_w, kn_w);

    // [4] ckv weight transpose, [5] CKV GEMM with fused c_k RMSNorm+ReLU
    conv_w_t<<<dim3(2 * DMODEL / 32, DMODEL / 32), wblk>>>(w_ckv, p_wh + W_CKV, 2 * DMODEL);
    gemm_mma_h<<<dim3(2 * DMODEL / BN, YR / BM), blk, GEMM_SMEM>>>(
        p_yh, p_wh + W_CKV, b_ckv, p_ckv, 2 * DMODEL, 1024, ckn_w, ckn_w);

    // [6] out weight transpose
    conv_w_t<<<dim3(DMODEL / 32, DMODEL / 32), wblk>>>(w_out, p_wh + W_OUT, DMODEL);

    // [7..8] kv + k_sum
    kv_accum<<<dim3(NCHUNK, 64), blk>>>(p_qkv, p_ckv, p_kvp, p_ksp);
    kv_reduce<<<(64 * DH * DH + 255) / 256, blk>>>(p_kvp, p_ksp, p_kv, p_ksum);

    // [9] attn (writes fp16 directly into x-side buffer)
    attn_apply<<<dim3(NTOK / 64, 64), blk>>>(p_qkv, p_kv, p_ksum, p_ah);

    // [10] output GEMM (fp32 direct-store epilogue)
    gemm_mma_f<<<dim3(DMODEL / BN, MR / BM), blk, GEMM_SMEM>>>(
        p_ah, p_wh + W_OUT, b_out, out, DMODEL);
}